// round 7
// baseline (speedup 1.0000x reference)
#include <cuda_runtime.h>
#include <cuda_bf16.h>
#include <math.h>

#define NB   8
#define NC   128
#define LL   4096
#define DM   32
#define DI   64
#define DS   64
#define CHK  64
#define NCHK 64

__device__ float g_out1[NB*NC*LL];
__device__ float g_act [NB*NC*LL];
__device__ float g_s   [NB*LL*DM];
__device__ float g_z   [2*NB*LL*DI];
__device__ float g_X   [2*NB*LL*DI];
__device__ float g_Bm  [2*NB*LL*DS];
__device__ float g_Cm  [2*NB*LL*DS];
__device__ float g_dt  [2*NB*LL];
__device__ float g_la  [2*NB*LL];
__device__ float g_alpha[2*NB*NCHK];
__device__ float g_S   [2*NB*NCHK*DI*DS];
__device__ float g_Hp  [2*NB*NCHK*DI*DS];
__device__ float g_ym  [2*NB*LL*DM];
__device__ float g_o2  [NB*NC*LL];
__device__ float g_ns[NC], g_nb[NC];
__device__ float g_Ap[NC*NC];
__device__ float g_bp[NC];

__device__ __forceinline__ float siluf(float v){ return v / (1.f + __expf(-v)); }

// out[b,o,l] = f( sum_i A[i,o]*Xin[b,i,l] + bias[o] )
template<int MODE>
__global__ void __launch_bounds__(256) gemm_cn_kernel(
    const float* __restrict__ Aext, const float* __restrict__ Xext,
    const float* __restrict__ bext, const float* __restrict__ resx,
    float* __restrict__ outext)
{
    const float* A    = (MODE==0) ? Aext : g_Ap;
    const float* Xin  = (MODE==0) ? Xext : g_o2;
    const float* bias = (MODE==0) ? bext : g_bp;
    float*       out  = (MODE==0) ? g_out1 : outext;

    const int lt = blockIdx.x*64, ot = blockIdx.y*64, b = blockIdx.z;
    __shared__ float sA[16][68];
    __shared__ float sX[16][68];
    const int tid = threadIdx.x;
    const int tl = (tid & 15)*4, to = (tid >> 4)*4;
    float acc[4][4] = {};
    const float* Xb = Xin + (size_t)b*NC*LL;

    for (int k0 = 0; k0 < 128; k0 += 16) {
        for (int i = tid; i < 16*64; i += 256) {
            int kk = i>>6, j = i&63;
            sA[kk][j] = A[(k0+kk)*128 + ot + j];
            sX[kk][j] = Xb[(size_t)(k0+kk)*LL + lt + j];
        }
        __syncthreads();
        #pragma unroll
        for (int kk = 0; kk < 16; kk++) {
            float a0=sA[kk][to],a1=sA[kk][to+1],a2=sA[kk][to+2],a3=sA[kk][to+3];
            float x0=sX[kk][tl],x1=sX[kk][tl+1],x2=sX[kk][tl+2],x3=sX[kk][tl+3];
            acc[0][0]+=a0*x0; acc[0][1]+=a0*x1; acc[0][2]+=a0*x2; acc[0][3]+=a0*x3;
            acc[1][0]+=a1*x0; acc[1][1]+=a1*x1; acc[1][2]+=a1*x2; acc[1][3]+=a1*x3;
            acc[2][0]+=a2*x0; acc[2][1]+=a2*x1; acc[2][2]+=a2*x2; acc[2][3]+=a2*x3;
            acc[3][0]+=a3*x0; acc[3][1]+=a3*x1; acc[3][2]+=a3*x2; acc[3][3]+=a3*x3;
        }
        __syncthreads();
    }
    #pragma unroll
    for (int i = 0; i < 4; i++) {
        int o = ot + to + i;
        float bv = bias[o];
        #pragma unroll
        for (int j = 0; j < 4; j++) {
            size_t idx = ((size_t)b*NC + o)*LL + lt + tl + j;
            float v = acc[i][j] + bv;
            if (MODE == 1) {
                float g = 1.f/(1.f + __expf(-v));
                float xv = resx[idx];
                v = g*xv + xv;
            }
            out[idx] = v;
        }
    }
}

__global__ void __launch_bounds__(256) dwconv_kernel(
    const float* __restrict__ w, const float* __restrict__ bias)
{
    const int b = blockIdx.z, c = blockIdx.y, st = blockIdx.x;
    __shared__ float tile[18][66];
    const float* inp = g_out1 + ((size_t)b*NC + c)*LL;
    const int h0 = st*16;
    for (int i = threadIdx.x; i < 18*66; i += 256) {
        int r = i/66, q = i%66;
        int h = h0 + r - 1, wq = q - 1;
        tile[r][q] = (h>=0 && h<64 && wq>=0 && wq<64) ? inp[h*64+wq] : 0.f;
    }
    __syncthreads();
    const float* wc = w + c*9;
    const float bb = bias[c];
    for (int i = threadIdx.x; i < 16*64; i += 256) {
        int r = i>>6, q = i&63;
        float v = wc[0]*tile[r][q]   + wc[1]*tile[r][q+1]   + wc[2]*tile[r][q+2]
                + wc[3]*tile[r+1][q] + wc[4]*tile[r+1][q+1] + wc[5]*tile[r+1][q+2]
                + wc[6]*tile[r+2][q] + wc[7]*tile[r+2][q+1] + wc[8]*tile[r+2][q+2] + bb;
        g_act[((size_t)b*NC + c)*LL + (h0+r)*64 + q] = siluf(v);
    }
}

__global__ void __launch_bounds__(128) fcin_kernel(const float* __restrict__ w)
{
    __shared__ float sw[NC*DM];
    for (int i = threadIdx.x; i < NC*DM; i += 128) sw[i] = w[i];
    __syncthreads();
    const int b = blockIdx.x / 32;
    const int l = (blockIdx.x % 32)*128 + threadIdx.x;
    const float* ap = g_act + (size_t)b*NC*LL + l;
    float acc[DM] = {};
    for (int c = 0; c < NC; c++) {
        float v = ap[(size_t)c*LL];
        #pragma unroll
        for (int d = 0; d < DM; d++) acc[d] += v*sw[c*DM+d];
    }
    float* sp = g_s + ((size_t)b*LL + l)*DM;
    #pragma unroll
    for (int d = 0; d < DM; d++) sp[d] = acc[d];
}

__global__ void __launch_bounds__(256) chunkprep_kernel(
    const float* __restrict__ W_in, const float* __restrict__ convw,
    const float* __restrict__ convb, const float* __restrict__ dtb,
    const float* __restrict__ Alog)
{
    extern __shared__ float sm[];
    float* sS  = sm;             // 67*33
    float* sW  = sS + 67*33;     // 32*68
    float* sT  = sW + 32*68;     // 67*68
    float* sX  = sT + 67*68;     // 64*68
    float* sB  = sX + 64*68;     // 64*68
    float* sdt = sB + 64*68;     // 64
    float* sla = sdt + 64;       // 64
    float* swt = sla + 64;       // 64

    const int c = blockIdx.x, b = blockIdx.y, d = blockIdx.z;
    const int tid = threadIdx.x;
    const int t0 = c*CHK;
    const int bd = d*NB + b;

    for (int i = tid; i < 67*32; i += 256) {
        int u = i>>5, k = i&31;
        int t = t0 + u - 3;
        float v = 0.f;
        if (t >= 0) {
            int l = d ? (LL-1-t) : t;
            v = g_s[((size_t)b*LL + l)*DM + k];
        }
        sS[u*33+k] = v;
    }
    const float* Wd = W_in + d*32*257;

    for (int tile = 0; tile < 4; tile++) {
        __syncthreads();
        for (int i = tid; i < 32*64; i += 256) {
            int k = i>>6, j = i&63;
            sW[k*68+j] = Wd[k*257 + tile*64 + j];
        }
        __syncthreads();
        for (int i = tid; i < 67*64; i += 256) {
            int u = i>>6, j = i&63;
            float a = 0.f;
            #pragma unroll
            for (int k = 0; k < 32; k++) a += sS[u*33+k]*sW[k*68+j];
            sT[u*68+j] = a;
        }
        __syncthreads();
        if (tile == 0) {
            for (int i = tid; i < 64*64; i += 256) {
                int t = i>>6, j = i&63;
                g_z[((size_t)bd*LL + t0 + t)*DI + j] = sT[(t+3)*68+j];
            }
        } else {
            for (int i = tid; i < 64*64; i += 256) {
                int t = i>>6, j = i&63;
                int ch = (tile-1)*64 + j;
                const float* cw = convw + (d*192 + ch)*4;
                float v = cw[0]*sT[t*68+j] + cw[1]*sT[(t+1)*68+j]
                        + cw[2]*sT[(t+2)*68+j] + cw[3]*sT[(t+3)*68+j]
                        + convb[d*192 + ch];
                v = siluf(v);
                size_t gi = ((size_t)bd*LL + t0 + t)*DI + j;
                if      (tile == 1) { sX[t*68+j] = v; g_X[gi]  = v; }
                else if (tile == 2) { sB[t*68+j] = v; g_Bm[gi] = v; }
                else                {                 g_Cm[gi] = v; }
            }
        }
    }
    __syncthreads();

    if (tid < 64) {
        float a = 0.f;
        #pragma unroll
        for (int k = 0; k < 32; k++) a += sS[(tid+3)*33+k]*Wd[k*257+256];
        a += dtb[d];
        float dt = (a > 20.f) ? a : log1pf(__expf(a));
        sdt[tid] = dt;
        g_dt[(size_t)bd*LL + t0 + tid] = dt;
    }
    __syncthreads();
    if (tid == 0) {
        float eA = __expf(Alog[d]);
        float run = 0.f;
        for (int t = 0; t < 64; t++) { run -= sdt[t]*eA; sla[t] = run; }
        g_alpha[bd*NCHK + c] = __expf(run);
    }
    __syncthreads();
    if (tid < 64) {
        swt[tid] = __expf(sla[63] - sla[tid])*sdt[tid];
        g_la[(size_t)bd*LL + t0 + tid] = sla[tid];
    }
    __syncthreads();
    for (int i = tid; i < 64*64; i += 256) {
        int s_ = i>>6;
        sX[s_*68 + (i&63)] *= swt[s_];
    }
    __syncthreads();
    float* Sp = g_S + ((size_t)bd*NCHK + c)*4096;
    for (int i = tid; i < 64*64; i += 256) {
        int p = i>>6, n = i&63;
        float a = 0.f;
        #pragma unroll
        for (int s_ = 0; s_ < 64; s_++) a += sX[s_*68+p]*sB[s_*68+n];
        Sp[i] = a;
    }
}

__global__ void __launch_bounds__(256) hscan_kernel()
{
    const int bd = blockIdx.y;
    const int cell = blockIdx.x*256 + threadIdx.x;
    const float* Sp = g_S  + (size_t)bd*NCHK*4096 + cell;
    float*       Hp = g_Hp + (size_t)bd*NCHK*4096 + cell;
    const float* al = g_alpha + bd*NCHK;
    float h = 0.f;
    #pragma unroll 8
    for (int c = 0; c < NCHK; c++) {
        Hp[(size_t)c*4096] = h;
        h = al[c]*h + Sp[(size_t)c*4096];
    }
}

__global__ void __launch_bounds__(256) chunkattn_kernel(
    const float* __restrict__ Wout, const float* __restrict__ normw,
    const float* __restrict__ Dp)
{
    extern __shared__ float sm2[];
    float* sC   = sm2;           // 64*68
    float* sO   = sC + 64*68;    // 64*68 : B, then Hprev
    float* sG   = sO + 64*68;    // 64*68 : G, then silu(z)
    float* sX   = sG + 64*68;    // 64*68 : X, then gated Y
    float* sWo  = sX + 64*68;    // 64*36
    float* snw  = sWo + 64*36;
    float* srms = snw + 64;
    float* slaL = srms + 64;
    float* sdtL = slaL + 64;
    float* sef  = sdtL + 64;

    const int c = blockIdx.x, b = blockIdx.y, d = blockIdx.z;
    const int tid = threadIdx.x;
    const int bd = d*NB + b;
    const int t0 = c*CHK;
    const size_t base = ((size_t)bd*LL + t0)*DI;

    for (int i = tid; i < 64*64; i += 256) {
        int t = i>>6, n = i&63;
        sC[t*68+n] = g_Cm[base+i];
        sO[t*68+n] = g_Bm[base+i];
        sX[t*68+n] = g_X [base+i];
    }
    for (int i = tid; i < 64*32; i += 256)
        sWo[(i>>5)*36 + (i&31)] = Wout[d*2048 + i];
    if (tid < 64) {
        snw[tid]  = normw[d*64 + tid];
        slaL[tid] = g_la[(size_t)bd*LL + t0 + tid];
        sdtL[tid] = g_dt[(size_t)bd*LL + t0 + tid];
        sef[tid]  = __expf(slaL[tid]);
    }
    __syncthreads();

    const int tr = tid>>4, tc = tid&15;
    const int ti = tr*4, sj = tc*4;

    // pass1: M[t][s] = C_t . B_s
    float m[4][4] = {};
    for (int n = 0; n < 64; n++) {
        float av[4], bv[4];
        #pragma unroll
        for (int i = 0; i < 4; i++){ av[i]=sC[(ti+i)*68+n]; bv[i]=sO[(sj+i)*68+n]; }
        #pragma unroll
        for (int i = 0; i < 4; i++)
            #pragma unroll
            for (int j = 0; j < 4; j++) m[i][j] += av[i]*bv[j];
    }
    #pragma unroll
    for (int i = 0; i < 4; i++)
        #pragma unroll
        for (int j = 0; j < 4; j++) {
            int t = ti+i, s = sj+j;
            sG[t*68+s] = (t >= s) ? m[i][j]*sdtL[s]*__expf(slaL[t]-slaL[s]) : 0.f;
        }
    __syncthreads();

    for (int i = tid; i < 64*64; i += 256) {
        int t = i>>6;
        sC[t*68 + (i&63)] *= sef[t];
    }
    {
        const float* Hp = g_Hp + ((size_t)bd*NCHK + c)*4096;
        for (int i = tid; i < 64*64; i += 256) sO[(i>>6)*68 + (i&63)] = Hp[i];
    }
    __syncthreads();

    const float Dv = Dp[d];
    float y[4][4];
    #pragma unroll
    for (int i = 0; i < 4; i++)
        #pragma unroll
        for (int j = 0; j < 4; j++) y[i][j] = Dv*sX[(ti+i)*68 + sj+j];
    // pass2: Y += G @ X
    for (int s = 0; s < 64; s++) {
        float gv[4], xv[4];
        #pragma unroll
        for (int i = 0; i < 4; i++) gv[i] = sG[(ti+i)*68+s];
        #pragma unroll
        for (int j = 0; j < 4; j++) xv[j] = sX[s*68+sj+j];
        #pragma unroll
        for (int i = 0; i < 4; i++)
            #pragma unroll
            for (int j = 0; j < 4; j++) y[i][j] += gv[i]*xv[j];
    }
    // pass3: Y += (exp(la)*C) @ Hprev^T
    for (int n = 0; n < 64; n++) {
        float av[4], hv[4];
        #pragma unroll
        for (int i = 0; i < 4; i++){ av[i]=sC[(ti+i)*68+n]; hv[i]=sO[(sj+i)*68+n]; }
        #pragma unroll
        for (int i = 0; i < 4; i++)
            #pragma unroll
            for (int j = 0; j < 4; j++) y[i][j] += av[i]*hv[j];
    }
    __syncthreads();
    for (int i = tid; i < 64*64; i += 256)
        sG[(i>>6)*68 + (i&63)] = siluf(g_z[base+i]);
    __syncthreads();
    #pragma unroll
    for (int i = 0; i < 4; i++)
        #pragma unroll
        for (int j = 0; j < 4; j++) {
            y[i][j] *= sG[(ti+i)*68 + sj+j];
            sX[(ti+i)*68 + sj+j] = y[i][j];
        }
    __syncthreads();
    if (tid < 64) {
        float ss = 0.f;
        #pragma unroll
        for (int p = 0; p < 64; p++){ float v = sX[tid*68+p]; ss += v*v; }
        srms[tid] = rsqrtf(ss*(1.f/64.f) + 1e-5f);
    }
    __syncthreads();
    for (int i = tid; i < 64*64; i += 256) {
        int t = i>>6, p = i&63;
        sX[t*68+p] *= srms[t]*snw[p];
    }
    __syncthreads();
    {
        int t = tid>>2, q = (tid&3)*8;
        float acc[8] = {};
        for (int p = 0; p < 64; p++) {
            float v = sX[t*68+p];
            #pragma unroll
            for (int j = 0; j < 8; j++) acc[j] += v*sWo[p*36+q+j];
        }
        int l = d ? (LL-1-(t0+t)) : (t0+t);
        float* yp = g_ym + ((size_t)bd*LL + l)*DM + q;
        #pragma unroll
        for (int j = 0; j < 8; j++) yp[j] = acc[j];
    }
}

__global__ void __launch_bounds__(256) fcout_kernel(const float* __restrict__ W)
{
    __shared__ float sY[32][68];
    __shared__ float sW[32][68];
    const int lt = blockIdx.x*64, ct = blockIdx.y*64, b = blockIdx.z;
    const int tid = threadIdx.x;
    for (int i = tid; i < 32*64; i += 256) {
        int k = i>>6, j = i&63;
        size_t i0 = ((size_t)b*LL + lt + j)*DM + k;
        sY[k][j] = g_ym[i0] + g_ym[(size_t)NB*LL*DM + i0];
        sW[k][j] = W[k*128 + ct + j];
    }
    __syncthreads();
    const int tl = (tid&15)*4, to = (tid>>4)*4;
    float acc[4][4] = {};
    #pragma unroll
    for (int k = 0; k < 32; k++) {
        float a0=sW[k][to],a1=sW[k][to+1],a2=sW[k][to+2],a3=sW[k][to+3];
        float x0=sY[k][tl],x1=sY[k][tl+1],x2=sY[k][tl+2],x3=sY[k][tl+3];
        acc[0][0]+=a0*x0; acc[0][1]+=a0*x1; acc[0][2]+=a0*x2; acc[0][3]+=a0*x3;
        acc[1][0]+=a1*x0; acc[1][1]+=a1*x1; acc[1][2]+=a1*x2; acc[1][3]+=a1*x3;
        acc[2][0]+=a2*x0; acc[2][1]+=a2*x1; acc[2][2]+=a2*x2; acc[2][3]+=a2*x3;
        acc[3][0]+=a3*x0; acc[3][1]+=a3*x1; acc[3][2]+=a3*x2; acc[3][3]+=a3*x3;
    }
    #pragma unroll
    for (int i = 0; i < 4; i++)
        #pragma unroll
        for (int j = 0; j < 4; j++)
            g_o2[((size_t)b*NC + ct+to+i)*LL + lt+tl+j] = acc[i][j];
}

__global__ void __launch_bounds__(256) bnstats_kernel(
    const float* __restrict__ bng, const float* __restrict__ bnb)
{
    __shared__ float s1[256], s2[256];
    const int c = blockIdx.x, tid = threadIdx.x;
    float sum = 0.f, sq = 0.f;
    for (int b = 0; b < NB; b++) {
        const float* pp = g_o2 + ((size_t)b*NC + c)*LL;
        for (int i = tid; i < LL; i += 256) { float v = pp[i]; sum += v; sq += v*v; }
    }
    s1[tid] = sum; s2[tid] = sq;
    __syncthreads();
    for (int st = 128; st > 0; st >>= 1) {
        if (tid < st) { s1[tid] += s1[tid+st]; s2[tid] += s2[tid+st]; }
        __syncthreads();
    }
    if (tid == 0) {
        float inv = 1.f/(float)(NB*LL);
        float mu  = s1[0]*inv;
        float var = s2[0]*inv - mu*mu;
        float ns  = bng[c]*rsqrtf(var + 1e-5f);
        g_ns[c] = ns;
        g_nb[c] = bnb[c] - mu*ns;
    }
}

__global__ void foldA_kernel(const float* __restrict__ w)
{
    int i = blockIdx.x, o = threadIdx.x;
    g_Ap[i*128+o] = g_ns[i]*w[i*128+o];
}
__global__ void foldB_kernel(const float* __restrict__ w, const float* __restrict__ b4)
{
    int o = threadIdx.x;
    float s = b4[o];
    for (int i = 0; i < 128; i++) s += g_nb[i]*w[i*128+o];
    g_bp[o] = s;
}

extern "C" void kernel_launch(void* const* d_in, const int* in_sizes, int n_in,
                              void* d_out, int out_size)
{
    const float* x      = (const float*)d_in[0];
    const float* lin1_w = (const float*)d_in[1];
    const float* lin1_b = (const float*)d_in[2];
    const float* dw_w   = (const float*)d_in[3];
    const float* dw_b   = (const float*)d_in[4];
    const float* fcin_w = (const float*)d_in[5];
    const float* W_in   = (const float*)d_in[6];
    const float* convw  = (const float*)d_in[7];
    const float* convb  = (const float*)d_in[8];
    const float* dtb    = (const float*)d_in[9];
    const float* Alog   = (const float*)d_in[10];
    const float* Dp     = (const float*)d_in[11];
    const float* normw  = (const float*)d_in[12];
    const float* Wout   = (const float*)d_in[13];
    const float* fcow   = (const float*)d_in[14];
    const float* bng    = (const float*)d_in[15];
    const float* bnb    = (const float*)d_in[16];
    const float* c4w    = (const float*)d_in[17];
    const float* c4b    = (const float*)d_in[18];
    float* out = (float*)d_out;

    const int CP_SMEM = (67*33 + 32*68 + 67*68 + 2*64*68 + 3*64)*4;
    const int CA_SMEM = (4*64*68 + 64*36 + 5*64)*4;
    cudaFuncSetAttribute(chunkprep_kernel, cudaFuncAttributeMaxDynamicSharedMemorySize, CP_SMEM);
    cudaFuncSetAttribute(chunkattn_kernel, cudaFuncAttributeMaxDynamicSharedMemorySize, CA_SMEM);

    gemm_cn_kernel<0><<<dim3(64,2,NB), 256>>>(lin1_w, x, lin1_b, nullptr, nullptr);
    dwconv_kernel<<<dim3(4,NC,NB), 256>>>(dw_w, dw_b);
    fcin_kernel<<<NB*32, 128>>>(fcin_w);
    chunkprep_kernel<<<dim3(NCHK,NB,2), 256, CP_SMEM>>>(W_in, convw, convb, dtb, Alog);
    hscan_kernel<<<dim3(16,16), 256>>>();
    chunkattn_kernel<<<dim3(NCHK,NB,2), 256, CA_SMEM>>>(Wout, normw, Dp);
    fcout_kernel<<<dim3(64,2,NB), 256>>>(fcow);
    bnstats_kernel<<<NC, 256>>>(bng, bnb);
    foldA_kernel<<<NC, NC>>>(c4w);
    foldB_kernel<<<1, NC>>>(c4w, c4b);
    gemm_cn_kernel<1><<<dim3(64,2,NB), 256>>>(nullptr, nullptr, nullptr, x, out);
}

// round 8
// speedup vs baseline: 1.3871x; 1.3871x over previous
#include <cuda_runtime.h>
#include <cuda_bf16.h>
#include <math.h>

#define NB   8
#define NC   128
#define LL   4096
#define DM   32
#define DI   64
#define DS   64
#define CHK  64
#define NCHK 64

__device__ float g_out1[NB*NC*LL];
__device__ float g_act [NB*NC*LL];
__device__ float g_s   [NB*LL*DM];
__device__ float g_z   [2*NB*LL*DI];
__device__ float g_X   [2*NB*LL*DI];
__device__ float g_Bm  [2*NB*LL*DS];
__device__ float g_Cm  [2*NB*LL*DS];
__device__ float g_dt  [2*NB*LL];
__device__ float g_la  [2*NB*LL];
__device__ float g_alpha[2*NB*NCHK];
__device__ float g_S   [2*NB*NCHK*DI*DS];
__device__ float g_Hp  [2*NB*NCHK*DI*DS];
__device__ float g_ym  [2*NB*LL*DM];
__device__ float g_o2  [NB*NC*LL];
__device__ float g_red [NC*NB*2];
__device__ float g_ns[NC], g_nb[NC];
__device__ float g_Ap[NC*NC];
__device__ float g_bp[NC];

__device__ __forceinline__ float siluf(float v){ return v / (1.f + __expf(-v)); }

// out[b,o,l] = f( sum_i A[i,o]*Xin[b,i,l] + bias[o] )
template<int MODE>
__global__ void __launch_bounds__(256) gemm_cn_kernel(
    const float* __restrict__ Aext, const float* __restrict__ Xext,
    const float* __restrict__ bext, const float* __restrict__ resx,
    float* __restrict__ outext)
{
    const float* A    = (MODE==0) ? Aext : g_Ap;
    const float* Xin  = (MODE==0) ? Xext : g_o2;
    const float* bias = (MODE==0) ? bext : g_bp;
    float*       out  = (MODE==0) ? g_out1 : outext;

    const int lt = blockIdx.x*64, ot = blockIdx.y*64, b = blockIdx.z;
    __shared__ float sA[32][68];
    __shared__ float sX[32][68];
    const int tid = threadIdx.x;
    const int tl = (tid & 15)*4, to = (tid >> 4)*4;
    float acc[4][4] = {};
    const float* Xb = Xin + (size_t)b*NC*LL;

    for (int k0 = 0; k0 < 128; k0 += 32) {
        for (int i = tid; i < 32*64; i += 256) {
            int kk = i>>6, j = i&63;
            sA[kk][j] = A[(k0+kk)*128 + ot + j];
            sX[kk][j] = Xb[(size_t)(k0+kk)*LL + lt + j];
        }
        __syncthreads();
        #pragma unroll
        for (int kk = 0; kk < 32; kk++) {
            float a0=sA[kk][to],a1=sA[kk][to+1],a2=sA[kk][to+2],a3=sA[kk][to+3];
            float x0=sX[kk][tl],x1=sX[kk][tl+1],x2=sX[kk][tl+2],x3=sX[kk][tl+3];
            acc[0][0]+=a0*x0; acc[0][1]+=a0*x1; acc[0][2]+=a0*x2; acc[0][3]+=a0*x3;
            acc[1][0]+=a1*x0; acc[1][1]+=a1*x1; acc[1][2]+=a1*x2; acc[1][3]+=a1*x3;
            acc[2][0]+=a2*x0; acc[2][1]+=a2*x1; acc[2][2]+=a2*x2; acc[2][3]+=a2*x3;
            acc[3][0]+=a3*x0; acc[3][1]+=a3*x1; acc[3][2]+=a3*x2; acc[3][3]+=a3*x3;
        }
        __syncthreads();
    }
    #pragma unroll
    for (int i = 0; i < 4; i++) {
        int o = ot + to + i;
        float bv = bias[o];
        #pragma unroll
        for (int j = 0; j < 4; j++) {
            size_t idx = ((size_t)b*NC + o)*LL + lt + tl + j;
            float v = acc[i][j] + bv;
            if (MODE == 1) {
                float g = 1.f/(1.f + __expf(-v));
                float xv = resx[idx];
                v = g*xv + xv;
            }
            out[idx] = v;
        }
    }
}

__global__ void __launch_bounds__(256) dwconv_kernel(
    const float* __restrict__ w, const float* __restrict__ bias)
{
    const int b = blockIdx.z, c = blockIdx.y, st = blockIdx.x;
    __shared__ float tile[18][66];
    const float* inp = g_out1 + ((size_t)b*NC + c)*LL;
    const int h0 = st*16;
    for (int i = threadIdx.x; i < 18*66; i += 256) {
        int r = i/66, q = i%66;
        int h = h0 + r - 1, wq = q - 1;
        tile[r][q] = (h>=0 && h<64 && wq>=0 && wq<64) ? inp[h*64+wq] : 0.f;
    }
    __syncthreads();
    const float* wc = w + c*9;
    const float bb = bias[c];
    for (int i = threadIdx.x; i < 16*64; i += 256) {
        int r = i>>6, q = i&63;
        float v = wc[0]*tile[r][q]   + wc[1]*tile[r][q+1]   + wc[2]*tile[r][q+2]
                + wc[3]*tile[r+1][q] + wc[4]*tile[r+1][q+1] + wc[5]*tile[r+1][q+2]
                + wc[6]*tile[r+2][q] + wc[7]*tile[r+2][q+1] + wc[8]*tile[r+2][q+2] + bb;
        g_act[((size_t)b*NC + c)*LL + (h0+r)*64 + q] = siluf(v);
    }
}

__global__ void __launch_bounds__(128) fcin_kernel(const float* __restrict__ w)
{
    __shared__ float sw[NC*DM];
    for (int i = threadIdx.x; i < NC*DM; i += 128) sw[i] = w[i];
    __syncthreads();
    const int b = blockIdx.x / 32;
    const int l = (blockIdx.x % 32)*128 + threadIdx.x;
    const float* ap = g_act + (size_t)b*NC*LL + l;
    float acc[DM] = {};
    for (int c = 0; c < NC; c++) {
        float v = ap[(size_t)c*LL];
        #pragma unroll
        for (int d = 0; d < DM; d++) acc[d] += v*sw[c*DM+d];
    }
    float* sp = g_s + ((size_t)b*LL + l)*DM;
    #pragma unroll
    for (int d = 0; d < DM; d++) sp[d] = acc[d];
}

__global__ void __launch_bounds__(256) chunkprep_kernel(
    const float* __restrict__ W_in, const float* __restrict__ convw,
    const float* __restrict__ convb, const float* __restrict__ dtb,
    const float* __restrict__ Alog)
{
    extern __shared__ float sm[];
    float* sS  = sm;             // 67*33
    float* sW  = sS + 67*33;     // 32*68
    float* sT  = sW + 32*68;     // 67*68
    float* sX  = sT + 67*68;     // 64*68
    float* sB  = sX + 64*68;     // 64*68
    float* sdt = sB + 64*68;     // 64
    float* sla = sdt + 64;       // 64
    float* swt = sla + 64;       // 64

    const int c = blockIdx.x, b = blockIdx.y, d = blockIdx.z;
    const int tid = threadIdx.x;
    const int t0 = c*CHK;
    const int bd = d*NB + b;
    const int ti = (tid>>4)*4, sj = (tid&15)*4;

    for (int i = tid; i < 67*32; i += 256) {
        int u = i>>5, k = i&31;
        int t = t0 + u - 3;
        float v = 0.f;
        if (t >= 0) {
            int l = d ? (LL-1-t) : t;
            v = g_s[((size_t)b*LL + l)*DM + k];
        }
        sS[u*33+k] = v;
    }
    const float* Wd = W_in + d*32*257;

    for (int tile = 0; tile < 4; tile++) {
        __syncthreads();
        for (int i = tid; i < 32*64; i += 256) {
            int k = i>>6, j = i&63;
            sW[k*68+j] = Wd[k*257 + tile*64 + j];
        }
        __syncthreads();
        {
            // microtiled: T[0..63][0..63]
            float acc[4][4] = {};
            #pragma unroll
            for (int k = 0; k < 32; k++) {
                float av[4], bv[4];
                #pragma unroll
                for (int i = 0; i < 4; i++) av[i] = sS[(ti+i)*33+k];
                #pragma unroll
                for (int j = 0; j < 4; j++) bv[j] = sW[k*68+sj+j];
                #pragma unroll
                for (int i = 0; i < 4; i++)
                    #pragma unroll
                    for (int j = 0; j < 4; j++) acc[i][j] += av[i]*bv[j];
            }
            #pragma unroll
            for (int i = 0; i < 4; i++)
                #pragma unroll
                for (int j = 0; j < 4; j++) sT[(ti+i)*68+sj+j] = acc[i][j];
            // halo rows 64..66
            if (tid < 192) {
                int u = 64 + (tid>>6), j = tid&63;
                float a = 0.f;
                #pragma unroll
                for (int k = 0; k < 32; k++) a += sS[u*33+k]*sW[k*68+j];
                sT[u*68+j] = a;
            }
        }
        __syncthreads();
        if (tile == 0) {
            for (int i = tid; i < 64*64; i += 256) {
                int t = i>>6, j = i&63;
                g_z[((size_t)bd*LL + t0 + t)*DI + j] = sT[(t+3)*68+j];
            }
        } else {
            for (int i = tid; i < 64*64; i += 256) {
                int t = i>>6, j = i&63;
                int ch = (tile-1)*64 + j;
                const float* cw = convw + (d*192 + ch)*4;
                float v = cw[0]*sT[t*68+j] + cw[1]*sT[(t+1)*68+j]
                        + cw[2]*sT[(t+2)*68+j] + cw[3]*sT[(t+3)*68+j]
                        + convb[d*192 + ch];
                v = siluf(v);
                size_t gi = ((size_t)bd*LL + t0 + t)*DI + j;
                if      (tile == 1) { sX[t*68+j] = v; g_X[gi]  = v; }
                else if (tile == 2) { sB[t*68+j] = v; g_Bm[gi] = v; }
                else                {                 g_Cm[gi] = v; }
            }
        }
    }
    __syncthreads();

    if (tid < 64) {
        float a = 0.f;
        #pragma unroll
        for (int k = 0; k < 32; k++) a += sS[(tid+3)*33+k]*Wd[k*257+256];
        a += dtb[d];
        float dt = (a > 20.f) ? a : log1pf(__expf(a));
        sdt[tid] = dt;
        g_dt[(size_t)bd*LL + t0 + tid] = dt;
    }
    __syncthreads();
    if (tid == 0) {
        float eA = __expf(Alog[d]);
        float run = 0.f;
        for (int t = 0; t < 64; t++) { run -= sdt[t]*eA; sla[t] = run; }
        g_alpha[bd*NCHK + c] = __expf(run);
    }
    __syncthreads();
    if (tid < 64) {
        swt[tid] = __expf(sla[63] - sla[tid])*sdt[tid];
        g_la[(size_t)bd*LL + t0 + tid] = sla[tid];
    }
    __syncthreads();
    for (int i = tid; i < 64*64; i += 256) {
        int s_ = i>>6;
        sX[s_*68 + (i&63)] *= swt[s_];
    }
    __syncthreads();
    {
        // S[p][n] = sum_s wX[s][p]*B[s][n]  (microtiled)
        float acc[4][4] = {};
        #pragma unroll 8
        for (int s_ = 0; s_ < 64; s_++) {
            float av[4], bv[4];
            #pragma unroll
            for (int i = 0; i < 4; i++) av[i] = sX[s_*68+ti+i];
            #pragma unroll
            for (int j = 0; j < 4; j++) bv[j] = sB[s_*68+sj+j];
            #pragma unroll
            for (int i = 0; i < 4; i++)
                #pragma unroll
                for (int j = 0; j < 4; j++) acc[i][j] += av[i]*bv[j];
        }
        float* Sp = g_S + ((size_t)bd*NCHK + c)*4096;
        #pragma unroll
        for (int i = 0; i < 4; i++)
            #pragma unroll
            for (int j = 0; j < 4; j++) Sp[(ti+i)*64+sj+j] = acc[i][j];
    }
}

__global__ void __launch_bounds__(256) hscan_kernel()
{
    const int bd = blockIdx.y;
    const int cell = blockIdx.x*256 + threadIdx.x;
    const float* Sp = g_S  + (size_t)bd*NCHK*4096 + cell;
    float*       Hp = g_Hp + (size_t)bd*NCHK*4096 + cell;
    const float* al = g_alpha + bd*NCHK;
    float h = 0.f;
    #pragma unroll 8
    for (int c = 0; c < NCHK; c++) {
        Hp[(size_t)c*4096] = h;
        h = al[c]*h + Sp[(size_t)c*4096];
    }
}

#define ST 65
__global__ void __launch_bounds__(256) chunkattn_kernel(
    const float* __restrict__ Wout, const float* __restrict__ normw,
    const float* __restrict__ Dp)
{
    extern __shared__ float sm2[];
    float* sC   = sm2;            // 64*ST
    float* sBT  = sC + 64*ST;     // 64*ST : B^T [n][t], then Hprev^T [n][p]
    float* sG   = sBT + 64*ST;    // 64*ST : G, then silu(z)
    float* sX   = sG + 64*ST;     // 64*ST : X, then gated Y
    float* sWo  = sX + 64*ST;     // 64*33
    float* snw  = sWo + 64*33;
    float* srms = snw + 64;
    float* slaL = srms + 64;
    float* sdtL = slaL + 64;
    float* sef  = sdtL + 64;

    const int c = blockIdx.x, b = blockIdx.y, d = blockIdx.z;
    const int tid = threadIdx.x;
    const int bd = d*NB + b;
    const int t0 = c*CHK;
    const size_t base = ((size_t)bd*LL + t0)*DI;

    for (int i = tid; i < 64*64; i += 256) {
        int t = i>>6, n = i&63;
        sC[t*ST+n]  = g_Cm[base+i];
        sBT[n*ST+t] = g_Bm[base+i];
        sX[t*ST+n]  = g_X [base+i];
    }
    for (int i = tid; i < 64*32; i += 256)
        sWo[(i>>5)*33 + (i&31)] = Wout[d*2048 + i];
    if (tid < 64) {
        snw[tid]  = normw[d*64 + tid];
        slaL[tid] = g_la[(size_t)bd*LL + t0 + tid];
        sdtL[tid] = g_dt[(size_t)bd*LL + t0 + tid];
        sef[tid]  = __expf(slaL[tid]);
    }
    __syncthreads();

    const int ti = (tid>>4)*4, sj = (tid&15)*4;

    // pass1: M[t][s] = C_t . B_s (B transposed in smem)
    float m[4][4] = {};
    #pragma unroll 8
    for (int n = 0; n < 64; n++) {
        float av[4], bv[4];
        #pragma unroll
        for (int i = 0; i < 4; i++){ av[i]=sC[(ti+i)*ST+n]; bv[i]=sBT[n*ST+sj+i]; }
        #pragma unroll
        for (int i = 0; i < 4; i++)
            #pragma unroll
            for (int j = 0; j < 4; j++) m[i][j] += av[i]*bv[j];
    }
    #pragma unroll
    for (int i = 0; i < 4; i++)
        #pragma unroll
        for (int j = 0; j < 4; j++) {
            int t = ti+i, s = sj+j;
            sG[t*ST+s] = (t >= s) ? m[i][j]*sdtL[s]*__expf(slaL[t]-slaL[s]) : 0.f;
        }
    __syncthreads();

    for (int i = tid; i < 64*64; i += 256) {
        int t = i>>6;
        sC[t*ST + (i&63)] *= sef[t];
    }
    {
        const float* Hp = g_Hp + ((size_t)bd*NCHK + c)*4096;
        for (int i = tid; i < 64*64; i += 256)
            sBT[(i&63)*ST + (i>>6)] = Hp[i];   // HpT[n][p]
    }
    __syncthreads();

    const float Dv = Dp[d];
    float y[4][4];
    #pragma unroll
    for (int i = 0; i < 4; i++)
        #pragma unroll
        for (int j = 0; j < 4; j++) y[i][j] = Dv*sX[(ti+i)*ST + sj+j];
    // pass2: Y += G @ X
    #pragma unroll 8
    for (int s = 0; s < 64; s++) {
        float gv[4], xv[4];
        #pragma unroll
        for (int i = 0; i < 4; i++) gv[i] = sG[(ti+i)*ST+s];
        #pragma unroll
        for (int j = 0; j < 4; j++) xv[j] = sX[s*ST+sj+j];
        #pragma unroll
        for (int i = 0; i < 4; i++)
            #pragma unroll
            for (int j = 0; j < 4; j++) y[i][j] += gv[i]*xv[j];
    }
    // pass3: Y += (exp(la)*C) @ Hprev^T (Hp transposed in smem)
    #pragma unroll 8
    for (int n = 0; n < 64; n++) {
        float av[4], hv[4];
        #pragma unroll
        for (int i = 0; i < 4; i++){ av[i]=sC[(ti+i)*ST+n]; hv[i]=sBT[n*ST+sj+i]; }
        #pragma unroll
        for (int i = 0; i < 4; i++)
            #pragma unroll
            for (int j = 0; j < 4; j++) y[i][j] += av[i]*hv[j];
    }
    __syncthreads();
    for (int i = tid; i < 64*64; i += 256)
        sG[(i>>6)*ST + (i&63)] = siluf(g_z[base+i]);
    __syncthreads();
    #pragma unroll
    for (int i = 0; i < 4; i++)
        #pragma unroll
        for (int j = 0; j < 4; j++) {
            y[i][j] *= sG[(ti+i)*ST + sj+j];
            sX[(ti+i)*ST + sj+j] = y[i][j];
        }
    __syncthreads();
    if (tid < 64) {
        float ss = 0.f;
        #pragma unroll
        for (int p = 0; p < 64; p++){ float v = sX[tid*ST+p]; ss += v*v; }
        srms[tid] = rsqrtf(ss*(1.f/64.f) + 1e-5f);
    }
    __syncthreads();
    for (int i = tid; i < 64*64; i += 256) {
        int t = i>>6, p = i&63;
        sX[t*ST+p] *= srms[t]*snw[p];
    }
    __syncthreads();
    {
        int t = tid>>2, q = (tid&3)*8;
        float acc[8] = {};
        #pragma unroll 8
        for (int p = 0; p < 64; p++) {
            float v = sX[t*ST+p];
            #pragma unroll
            for (int j = 0; j < 8; j++) acc[j] += v*sWo[p*33+q+j];
        }
        int l = d ? (LL-1-(t0+t)) : (t0+t);
        float* yp = g_ym + ((size_t)bd*LL + l)*DM + q;
        #pragma unroll
        for (int j = 0; j < 8; j++) yp[j] = acc[j];
    }
}

__global__ void __launch_bounds__(256) fcout_kernel(const float* __restrict__ W)
{
    __shared__ float sY[32][68];
    __shared__ float sW[32][68];
    const int lt = blockIdx.x*64, ct = blockIdx.y*64, b = blockIdx.z;
    const int tid = threadIdx.x;
    for (int i = tid; i < 32*64; i += 256) {
        int k = i>>6, j = i&63;
        size_t i0 = ((size_t)b*LL + lt + j)*DM + k;
        sY[k][j] = g_ym[i0] + g_ym[(size_t)NB*LL*DM + i0];
        sW[k][j] = W[k*128 + ct + j];
    }
    __syncthreads();
    const int tl = (tid&15)*4, to = (tid>>4)*4;
    float acc[4][4] = {};
    #pragma unroll
    for (int k = 0; k < 32; k++) {
        float a0=sW[k][to],a1=sW[k][to+1],a2=sW[k][to+2],a3=sW[k][to+3];
        float x0=sY[k][tl],x1=sY[k][tl+1],x2=sY[k][tl+2],x3=sY[k][tl+3];
        acc[0][0]+=a0*x0; acc[0][1]+=a0*x1; acc[0][2]+=a0*x2; acc[0][3]+=a0*x3;
        acc[1][0]+=a1*x0; acc[1][1]+=a1*x1; acc[1][2]+=a1*x2; acc[1][3]+=a1*x3;
        acc[2][0]+=a2*x0; acc[2][1]+=a2*x1; acc[2][2]+=a2*x2; acc[2][3]+=a2*x3;
        acc[3][0]+=a3*x0; acc[3][1]+=a3*x1; acc[3][2]+=a3*x2; acc[3][3]+=a3*x3;
    }
    #pragma unroll
    for (int i = 0; i < 4; i++)
        #pragma unroll
        for (int j = 0; j < 4; j++)
            g_o2[((size_t)b*NC + ct+to+i)*LL + lt+tl+j] = acc[i][j];
}

__global__ void __launch_bounds__(128) bnstats1_kernel()
{
    const int c = blockIdx.x, b = blockIdx.y, tid = threadIdx.x;
    __shared__ float s1[128], s2[128];
    const float* pp = g_o2 + ((size_t)b*NC + c)*LL;
    float sum = 0.f, sq = 0.f;
    for (int i = tid; i < LL; i += 128) { float v = pp[i]; sum += v; sq += v*v; }
    s1[tid] = sum; s2[tid] = sq;
    __syncthreads();
    for (int st = 64; st > 0; st >>= 1) {
        if (tid < st) { s1[tid] += s1[tid+st]; s2[tid] += s2[tid+st]; }
        __syncthreads();
    }
    if (tid == 0) { g_red[(c*NB+b)*2] = s1[0]; g_red[(c*NB+b)*2+1] = s2[0]; }
}

__global__ void __launch_bounds__(128) bnstats2_kernel(
    const float* __restrict__ bng, const float* __restrict__ bnb)
{
    int c = threadIdx.x;
    float sum = 0.f, sq = 0.f;
    #pragma unroll
    for (int b = 0; b < NB; b++) { sum += g_red[(c*NB+b)*2]; sq += g_red[(c*NB+b)*2+1]; }
    float inv = 1.f/(float)(NB*LL);
    float mu  = sum*inv;
    float var = sq*inv - mu*mu;
    float ns  = bng[c]*rsqrtf(var + 1e-5f);
    g_ns[c] = ns;
    g_nb[c] = bnb[c] - mu*ns;
}

__global__ void foldA_kernel(const float* __restrict__ w)
{
    int i = blockIdx.x, o = threadIdx.x;
    g_Ap[i*128+o] = g_ns[i]*w[i*128+o];
}
__global__ void foldB_kernel(const float* __restrict__ w, const float* __restrict__ b4)
{
    int o = threadIdx.x;
    float s = b4[o];
    for (int i = 0; i < 128; i++) s += g_nb[i]*w[i*128+o];
    g_bp[o] = s;
}

extern "C" void kernel_launch(void* const* d_in, const int* in_sizes, int n_in,
                              void* d_out, int out_size)
{
    const float* x      = (const float*)d_in[0];
    const float* lin1_w = (const float*)d_in[1];
    const float* lin1_b = (const float*)d_in[2];
    const float* dw_w   = (const float*)d_in[3];
    const float* dw_b   = (const float*)d_in[4];
    const float* fcin_w = (const float*)d_in[5];
    const float* W_in   = (const float*)d_in[6];
    const float* convw  = (const float*)d_in[7];
    const float* convb  = (const float*)d_in[8];
    const float* dtb    = (const float*)d_in[9];
    const float* Alog   = (const float*)d_in[10];
    const float* Dp     = (const float*)d_in[11];
    const float* normw  = (const float*)d_in[12];
    const float* Wout   = (const float*)d_in[13];
    const float* fcow   = (const float*)d_in[14];
    const float* bng    = (const float*)d_in[15];
    const float* bnb    = (const float*)d_in[16];
    const float* c4w    = (const float*)d_in[17];
    const float* c4b    = (const float*)d_in[18];
    float* out = (float*)d_out;

    const int CP_SMEM = (67*33 + 32*68 + 67*68 + 2*64*68 + 3*64)*4;
    const int CA_SMEM = (4*64*ST + 64*33 + 5*64)*4;
    cudaFuncSetAttribute(chunkprep_kernel, cudaFuncAttributeMaxDynamicSharedMemorySize, CP_SMEM);
    cudaFuncSetAttribute(chunkattn_kernel, cudaFuncAttributeMaxDynamicSharedMemorySize, CA_SMEM);

    gemm_cn_kernel<0><<<dim3(64,2,NB), 256>>>(lin1_w, x, lin1_b, nullptr, nullptr);
    dwconv_kernel<<<dim3(4,NC,NB), 256>>>(dw_w, dw_b);
    fcin_kernel<<<NB*32, 128>>>(fcin_w);
    chunkprep_kernel<<<dim3(NCHK,NB,2), 256, CP_SMEM>>>(W_in, convw, convb, dtb, Alog);
    hscan_kernel<<<dim3(16,16), 256>>>();
    chunkattn_kernel<<<dim3(NCHK,NB,2), 256, CA_SMEM>>>(Wout, normw, Dp);
    fcout_kernel<<<dim3(64,2,NB), 256>>>(fcow);
    bnstats1_kernel<<<dim3(NC,NB), 128>>>();
    bnstats2_kernel<<<1, NC>>>(bng, bnb);
    foldA_kernel<<<NC, NC>>>(c4w);
    foldB_kernel<<<1, NC>>>(c4w, c4b);
    gemm_cn_kernel<1><<<dim3(64,2,NB), 256>>>(nullptr, nullptr, nullptr, x, out);
}

// round 10
// speedup vs baseline: 1.4340x; 1.0338x over previous
#include <cuda_runtime.h>
#include <cuda_bf16.h>
#include <math.h>

#define NB   8
#define NC   128
#define LL   4096
#define DM   32
#define DI   64
#define DS   64
#define CHK  64
#define NCHK 64

__device__ float g_out1[NB*NC*LL];
__device__ float g_act [NB*NC*LL];
__device__ float g_s   [NB*LL*DM];
__device__ float g_z   [2*NB*LL*DI];
__device__ float g_X   [2*NB*LL*DI];
__device__ float g_Bm  [2*NB*LL*DS];
__device__ float g_Cm  [2*NB*LL*DS];
__device__ float g_dt  [2*NB*LL];
__device__ float g_la  [2*NB*LL];
__device__ float g_alpha[2*NB*NCHK];
__device__ float g_S   [2*NB*NCHK*DI*DS];
__device__ float g_Hp  [2*NB*NCHK*DI*DS];
__device__ float g_ym  [2*NB*DM*LL];      // [bd][dm][l]
__device__ float g_o2  [NB*NC*LL];
__device__ float g_red [NC*NB*2];
__device__ float g_ns[NC], g_nb[NC];
__device__ float g_Ap[NC*NC];
__device__ float g_bp[NC];

__device__ __forceinline__ float siluf(float v){ return v / (1.f + __expf(-v)); }

// out[b,o,l] = f( sum_i A[i,o]*Xin[b,i,l] + bias[o] )
template<int MODE>
__global__ void __launch_bounds__(256) gemm_cn_kernel(
    const float* __restrict__ Aext, const float* __restrict__ Xext,
    const float* __restrict__ bext, const float* __restrict__ resx,
    float* __restrict__ outext)
{
    const float* A    = (MODE==0) ? Aext : g_Ap;
    const float* Xin  = (MODE==0) ? Xext : g_o2;
    const float* bias = (MODE==0) ? bext : g_bp;
    float*       out  = (MODE==0) ? g_out1 : outext;

    const int lt = blockIdx.x*64, ot = blockIdx.y*64, b = blockIdx.z;
    __shared__ __align__(16) float sA[32][68];
    __shared__ __align__(16) float sX[32][68];
    const int tid = threadIdx.x;
    const int tl = (tid & 15)*4, to = (tid >> 4)*4;
    float acc[4][4] = {};
    const float* Xb = Xin + (size_t)b*NC*LL;

    for (int k0 = 0; k0 < 128; k0 += 32) {
        for (int i = tid; i < 32*16; i += 256) {
            int kk = i>>4, j4 = (i&15)*4;
            *(float4*)&sA[kk][j4] = *(const float4*)&A[(k0+kk)*128 + ot + j4];
            *(float4*)&sX[kk][j4] = *(const float4*)&Xb[(size_t)(k0+kk)*LL + lt + j4];
        }
        __syncthreads();
        #pragma unroll
        for (int kk = 0; kk < 32; kk++) {
            float4 a = *(const float4*)&sA[kk][to];
            float4 x = *(const float4*)&sX[kk][tl];
            acc[0][0]+=a.x*x.x; acc[0][1]+=a.x*x.y; acc[0][2]+=a.x*x.z; acc[0][3]+=a.x*x.w;
            acc[1][0]+=a.y*x.x; acc[1][1]+=a.y*x.y; acc[1][2]+=a.y*x.z; acc[1][3]+=a.y*x.w;
            acc[2][0]+=a.z*x.x; acc[2][1]+=a.z*x.y; acc[2][2]+=a.z*x.z; acc[2][3]+=a.z*x.w;
            acc[3][0]+=a.w*x.x; acc[3][1]+=a.w*x.y; acc[3][2]+=a.w*x.z; acc[3][3]+=a.w*x.w;
        }
        __syncthreads();
    }
    #pragma unroll
    for (int i = 0; i < 4; i++) {
        int o = ot + to + i;
        float bv = bias[o];
        size_t idx = ((size_t)b*NC + o)*LL + lt + tl;
        float4 v;
        v.x = acc[i][0]+bv; v.y = acc[i][1]+bv; v.z = acc[i][2]+bv; v.w = acc[i][3]+bv;
        if (MODE == 1) {
            float4 xv = *(const float4*)&resx[idx];
            v.x = xv.x/(1.f+__expf(-v.x)) + xv.x;
            v.y = xv.y/(1.f+__expf(-v.y)) + xv.y;
            v.z = xv.z/(1.f+__expf(-v.z)) + xv.z;
            v.w = xv.w/(1.f+__expf(-v.w)) + xv.w;
        }
        *(float4*)&out[idx] = v;
    }
}

__global__ void __launch_bounds__(256) dwconv_kernel(
    const float* __restrict__ w, const float* __restrict__ bias)
{
    const int b = blockIdx.z, c = blockIdx.y, st = blockIdx.x;
    __shared__ float tile[18][66];
    const float* inp = g_out1 + ((size_t)b*NC + c)*LL;
    const int h0 = st*16;
    for (int i = threadIdx.x; i < 18*66; i += 256) {
        int r = i/66, q = i%66;
        int h = h0 + r - 1, wq = q - 1;
        tile[r][q] = (h>=0 && h<64 && wq>=0 && wq<64) ? inp[h*64+wq] : 0.f;
    }
    __syncthreads();
    const float* wc = w + c*9;
    const float bb = bias[c];
    for (int i = threadIdx.x; i < 16*64; i += 256) {
        int r = i>>6, q = i&63;
        float v = wc[0]*tile[r][q]   + wc[1]*tile[r][q+1]   + wc[2]*tile[r][q+2]
                + wc[3]*tile[r+1][q] + wc[4]*tile[r+1][q+1] + wc[5]*tile[r+1][q+2]
                + wc[6]*tile[r+2][q] + wc[7]*tile[r+2][q+1] + wc[8]*tile[r+2][q+2] + bb;
        g_act[((size_t)b*NC + c)*LL + (h0+r)*64 + q] = siluf(v);
    }
}

__global__ void __launch_bounds__(128) fcin_kernel(const float* __restrict__ w)
{
    __shared__ float sw[NC*DM];
    for (int i = threadIdx.x; i < NC*DM; i += 128) sw[i] = w[i];
    __syncthreads();
    const int b = blockIdx.x / 32;
    const int l = (blockIdx.x % 32)*128 + threadIdx.x;
    const float* ap = g_act + (size_t)b*NC*LL + l;
    float acc[DM] = {};
    for (int c = 0; c < NC; c++) {
        float v = ap[(size_t)c*LL];
        #pragma unroll
        for (int d = 0; d < DM; d++) acc[d] += v*sw[c*DM+d];
    }
    float* sp = g_s + ((size_t)b*LL + l)*DM;
    #pragma unroll
    for (int d = 0; d < DM; d++) sp[d] = acc[d];
}

#define SSS 36
__global__ void __launch_bounds__(256) chunkprep_kernel(
    const float* __restrict__ W_in, const float* __restrict__ convw,
    const float* __restrict__ convb, const float* __restrict__ dtb,
    const float* __restrict__ Alog)
{
    extern __shared__ float sm[];
    float* sS  = sm;                 // 67*36
    float* sW  = sS + 67*SSS;        // 32*68
    float* sT  = sW + 32*68;         // 67*68
    float* sX  = sT + 67*68;         // 64*68
    float* sB  = sX + 64*68;         // 64*68
    float* sdt = sB + 64*68;         // 64
    float* sla = sdt + 64;           // 64
    float* swt = sla + 64;           // 64

    const int c = blockIdx.x, b = blockIdx.y, d = blockIdx.z;
    const int tid = threadIdx.x;
    const int t0 = c*CHK;
    const int bd = d*NB + b;
    const int ti = (tid>>4)*4, sj = (tid&15)*4;

    for (int i = tid; i < 67*32; i += 256) {
        int u = i>>5, k = i&31;
        int t = t0 + u - 3;
        float v = 0.f;
        if (t >= 0) {
            int l = d ? (LL-1-t) : t;
            v = g_s[((size_t)b*LL + l)*DM + k];
        }
        sS[u*SSS+k] = v;
    }
    const float* Wd = W_in + d*32*257;

    for (int tile = 0; tile < 4; tile++) {
        __syncthreads();
        for (int i = tid; i < 32*64; i += 256) {
            int k = i>>6, j = i&63;
            sW[k*68+j] = Wd[k*257 + tile*64 + j];
        }
        __syncthreads();
        {
            float acc[4][4] = {};
            #pragma unroll
            for (int k0 = 0; k0 < 32; k0 += 4) {
                float a4[4][4];
                #pragma unroll
                for (int i = 0; i < 4; i++) {
                    float4 t4 = *(const float4*)&sS[(ti+i)*SSS+k0];
                    a4[i][0]=t4.x; a4[i][1]=t4.y; a4[i][2]=t4.z; a4[i][3]=t4.w;
                }
                #pragma unroll
                for (int kk = 0; kk < 4; kk++) {
                    float4 b4 = *(const float4*)&sW[(k0+kk)*68+sj];
                    #pragma unroll
                    for (int i = 0; i < 4; i++) {
                        acc[i][0] += a4[i][kk]*b4.x;
                        acc[i][1] += a4[i][kk]*b4.y;
                        acc[i][2] += a4[i][kk]*b4.z;
                        acc[i][3] += a4[i][kk]*b4.w;
                    }
                }
            }
            #pragma unroll
            for (int i = 0; i < 4; i++)
                *(float4*)&sT[(ti+i)*68+sj] = make_float4(acc[i][0],acc[i][1],acc[i][2],acc[i][3]);
            if (tid < 192) {
                int u = 64 + (tid>>6), j = tid&63;
                float a = 0.f;
                #pragma unroll
                for (int k = 0; k < 32; k++) a += sS[u*SSS+k]*sW[k*68+j];
                sT[u*68+j] = a;
            }
        }
        __syncthreads();
        if (tile == 0) {
            for (int i = tid; i < 64*64; i += 256) {
                int t = i>>6, j = i&63;
                g_z[((size_t)bd*LL + t0 + t)*DI + j] = sT[(t+3)*68+j];
            }
        } else {
            for (int i = tid; i < 64*64; i += 256) {
                int t = i>>6, j = i&63;
                int ch = (tile-1)*64 + j;
                const float* cw = convw + (d*192 + ch)*4;
                float v = cw[0]*sT[t*68+j] + cw[1]*sT[(t+1)*68+j]
                        + cw[2]*sT[(t+2)*68+j] + cw[3]*sT[(t+3)*68+j]
                        + convb[d*192 + ch];
                v = siluf(v);
                size_t gi = ((size_t)bd*LL + t0 + t)*DI + j;
                if      (tile == 1) { sX[t*68+j] = v; g_X[gi]  = v; }
                else if (tile == 2) { sB[t*68+j] = v; g_Bm[gi] = v; }
                else                {                 g_Cm[gi] = v; }
            }
        }
    }
    __syncthreads();

    if (tid < 64) {
        float a = 0.f;
        #pragma unroll
        for (int k = 0; k < 32; k++) a += sS[(tid+3)*SSS+k]*Wd[k*257+256];
        a += dtb[d];
        float dt = (a > 20.f) ? a : log1pf(__expf(a));
        sdt[tid] = dt;
        g_dt[(size_t)bd*LL + t0 + tid] = dt;
    }
    __syncthreads();
    if (tid == 0) {
        float eA = __expf(Alog[d]);
        float run = 0.f;
        for (int t = 0; t < 64; t++) { run -= sdt[t]*eA; sla[t] = run; }
        g_alpha[bd*NCHK + c] = __expf(run);
    }
    __syncthreads();
    if (tid < 64) {
        swt[tid] = __expf(sla[63] - sla[tid])*sdt[tid];
        g_la[(size_t)bd*LL + t0 + tid] = sla[tid];
    }
    __syncthreads();
    for (int i = tid; i < 64*64; i += 256) {
        int s_ = i>>6;
        sX[s_*68 + (i&63)] *= swt[s_];
    }
    __syncthreads();
    {
        // S[p][n] = sum_s wX[s][p]*B[s][n]
        float acc[4][4] = {};
        #pragma unroll 8
        for (int s_ = 0; s_ < 64; s_++) {
            float4 xa = *(const float4*)&sX[s_*68+ti];
            float4 bb = *(const float4*)&sB[s_*68+sj];
            acc[0][0]+=xa.x*bb.x; acc[0][1]+=xa.x*bb.y; acc[0][2]+=xa.x*bb.z; acc[0][3]+=xa.x*bb.w;
            acc[1][0]+=xa.y*bb.x; acc[1][1]+=xa.y*bb.y; acc[1][2]+=xa.y*bb.z; acc[1][3]+=xa.y*bb.w;
            acc[2][0]+=xa.z*bb.x; acc[2][1]+=xa.z*bb.y; acc[2][2]+=xa.z*bb.z; acc[2][3]+=xa.z*bb.w;
            acc[3][0]+=xa.w*bb.x; acc[3][1]+=xa.w*bb.y; acc[3][2]+=xa.w*bb.z; acc[3][3]+=xa.w*bb.w;
        }
        float* Sp = g_S + ((size_t)bd*NCHK + c)*4096;
        #pragma unroll
        for (int i = 0; i < 4; i++)
            *(float4*)&Sp[(ti+i)*64+sj] = make_float4(acc[i][0],acc[i][1],acc[i][2],acc[i][3]);
    }
}

__global__ void __launch_bounds__(256) hscan_kernel()
{
    const int bd = blockIdx.y;
    const int cell = (blockIdx.x*256 + threadIdx.x)*4;
    const float* Sp = g_S  + (size_t)bd*NCHK*4096 + cell;
    float*       Hp = g_Hp + (size_t)bd*NCHK*4096 + cell;
    const float* al = g_alpha + bd*NCHK;
    float4 h = make_float4(0.f,0.f,0.f,0.f);
    #pragma unroll 8
    for (int c = 0; c < NCHK; c++) {
        *(float4*)&Hp[(size_t)c*4096] = h;
        float a = al[c];
        float4 s = *(const float4*)&Sp[(size_t)c*4096];
        h.x = a*h.x + s.x; h.y = a*h.y + s.y; h.z = a*h.z + s.z; h.w = a*h.w + s.w;
    }
}

#define ST 68
__global__ void __launch_bounds__(256) chunkattn_kernel(
    const float* __restrict__ Wout, const float* __restrict__ normw,
    const float* __restrict__ Dp)
{
    extern __shared__ float sm2[];
    float* sC   = sm2;            // 64*ST
    float* sBT  = sC + 64*ST;     // 64*ST : B^T [n][t], then Hprev^T [n][p]
    float* sG   = sBT + 64*ST;    // 64*ST : G, then silu(z)
    float* sX   = sG + 64*ST;     // 64*ST : X, then gated Y
    float* sWo  = sX + 64*ST;     // 64*36
    float* snw  = sWo + 64*36;
    float* srms = snw + 64;
    float* slaL = srms + 64;
    float* sdtL = slaL + 64;
    float* sef  = sdtL + 64;

    const int c = blockIdx.x, b = blockIdx.y, d = blockIdx.z;
    const int tid = threadIdx.x;
    const int bd = d*NB + b;
    const int t0 = c*CHK;
    const size_t base = ((size_t)bd*LL + t0)*DI;

    for (int i = tid; i < 64*64; i += 256) {
        int t = i>>6, n = i&63;
        sC[t*ST+n]  = g_Cm[base+i];
        sBT[n*ST+t] = g_Bm[base+i];
        sX[t*ST+n]  = g_X [base+i];
    }
    for (int i = tid; i < 64*32; i += 256)
        sWo[(i>>5)*36 + (i&31)] = Wout[d*2048 + i];
    if (tid < 64) {
        snw[tid]  = normw[d*64 + tid];
        slaL[tid] = g_la[(size_t)bd*LL + t0 + tid];
        sdtL[tid] = g_dt[(size_t)bd*LL + t0 + tid];
        sef[tid]  = __expf(slaL[tid]);
    }
    __syncthreads();

    const int ti = (tid>>4)*4, sj = (tid&15)*4;

    // pass1: M[t][s] = C_t . B_s
    float m[4][4] = {};
    #pragma unroll
    for (int n0 = 0; n0 < 64; n0 += 4) {
        float c4[4][4];
        #pragma unroll
        for (int i = 0; i < 4; i++) {
            float4 t4 = *(const float4*)&sC[(ti+i)*ST+n0];
            c4[i][0]=t4.x; c4[i][1]=t4.y; c4[i][2]=t4.z; c4[i][3]=t4.w;
        }
        #pragma unroll
        for (int nn = 0; nn < 4; nn++) {
            float4 b4 = *(const float4*)&sBT[(n0+nn)*ST+sj];
            #pragma unroll
            for (int i = 0; i < 4; i++) {
                m[i][0] += c4[i][nn]*b4.x;
                m[i][1] += c4[i][nn]*b4.y;
                m[i][2] += c4[i][nn]*b4.z;
                m[i][3] += c4[i][nn]*b4.w;
            }
        }
    }
    #pragma unroll
    for (int i = 0; i < 4; i++) {
        int t = ti+i;
        float4 g;
        float* gp = &g.x;
        #pragma unroll
        for (int j = 0; j < 4; j++) {
            int s = sj+j;
            gp[j] = (t >= s) ? m[i][j]*sdtL[s]*__expf(slaL[t]-slaL[s]) : 0.f;
        }
        *(float4*)&sG[t*ST+sj] = g;
    }
    __syncthreads();

    for (int i = tid; i < 64*64; i += 256) {
        int t = i>>6;
        sC[t*ST + (i&63)] *= sef[t];
    }
    {
        const float* Hp = g_Hp + ((size_t)bd*NCHK + c)*4096;
        for (int i = tid; i < 64*64; i += 256)
            sBT[(i&63)*ST + (i>>6)] = Hp[i];   // HpT[n][p]
    }
    __syncthreads();

    const float Dv = Dp[d];
    float y[4][4];
    #pragma unroll
    for (int i = 0; i < 4; i++) {
        float4 x4 = *(const float4*)&sX[(ti+i)*ST+sj];
        y[i][0]=Dv*x4.x; y[i][1]=Dv*x4.y; y[i][2]=Dv*x4.z; y[i][3]=Dv*x4.w;
    }
    // pass2: Y += G @ X
    #pragma unroll
    for (int s0 = 0; s0 < 64; s0 += 4) {
        float g4[4][4];
        #pragma unroll
        for (int i = 0; i < 4; i++) {
            float4 t4 = *(const float4*)&sG[(ti+i)*ST+s0];
            g4[i][0]=t4.x; g4[i][1]=t4.y; g4[i][2]=t4.z; g4[i][3]=t4.w;
        }
        #pragma unroll
        for (int ss = 0; ss < 4; ss++) {
            float4 x4 = *(const float4*)&sX[(s0+ss)*ST+sj];
            #pragma unroll
            for (int i = 0; i < 4; i++) {
                y[i][0] += g4[i][ss]*x4.x;
                y[i][1] += g4[i][ss]*x4.y;
                y[i][2] += g4[i][ss]*x4.z;
                y[i][3] += g4[i][ss]*x4.w;
            }
        }
    }
    // pass3: Y += (exp(la)*C) @ Hprev^T
    #pragma unroll
    for (int n0 = 0; n0 < 64; n0 += 4) {
        float c4[4][4];
        #pragma unroll
        for (int i = 0; i < 4; i++) {
            float4 t4 = *(const float4*)&sC[(ti+i)*ST+n0];
            c4[i][0]=t4.x; c4[i][1]=t4.y; c4[i][2]=t4.z; c4[i][3]=t4.w;
        }
        #pragma unroll
        for (int nn = 0; nn < 4; nn++) {
            float4 h4 = *(const float4*)&sBT[(n0+nn)*ST+sj];
            #pragma unroll
            for (int i = 0; i < 4; i++) {
                y[i][0] += c4[i][nn]*h4.x;
                y[i][1] += c4[i][nn]*h4.y;
                y[i][2] += c4[i][nn]*h4.z;
                y[i][3] += c4[i][nn]*h4.w;
            }
        }
    }
    __syncthreads();
    for (int i = tid; i < 64*64; i += 256)
        sG[(i>>6)*ST + (i&63)] = siluf(g_z[base+i]);
    __syncthreads();
    #pragma unroll
    for (int i = 0; i < 4; i++) {
        float4 g4 = *(const float4*)&sG[(ti+i)*ST+sj];
        y[i][0]*=g4.x; y[i][1]*=g4.y; y[i][2]*=g4.z; y[i][3]*=g4.w;
        *(float4*)&sX[(ti+i)*ST+sj] = make_float4(y[i][0],y[i][1],y[i][2],y[i][3]);
    }
    __syncthreads();
    if (tid < 64) {
        float ss = 0.f;
        #pragma unroll
        for (int p = 0; p < 64; p++){ float v = sX[tid*ST+p]; ss += v*v; }
        srms[tid] = rsqrtf(ss*(1.f/64.f) + 1e-5f);
    }
    __syncthreads();
    for (int i = tid; i < 64*64; i += 256) {
        int t = i>>6, p = i&63;
        sX[t*ST+p] *= srms[t]*snw[p];
    }
    __syncthreads();
    {
        int t = tid>>2, q = (tid&3)*8;
        float acc[8] = {};
        #pragma unroll 8
        for (int p = 0; p < 64; p++) {
            float v = sX[t*ST+p];
            float4 w0 = *(const float4*)&sWo[p*36+q];
            float4 w1 = *(const float4*)&sWo[p*36+q+4];
            acc[0]+=v*w0.x; acc[1]+=v*w0.y; acc[2]+=v*w0.z; acc[3]+=v*w0.w;
            acc[4]+=v*w1.x; acc[5]+=v*w1.y; acc[6]+=v*w1.z; acc[7]+=v*w1.w;
        }
        int l = d ? (LL-1-(t0+t)) : (t0+t);
        #pragma unroll
        for (int j = 0; j < 8; j++)
            g_ym[((size_t)bd*DM + q + j)*LL + l] = acc[j];
    }
}

__global__ void __launch_bounds__(256) fcout_kernel(const float* __restrict__ W)
{
    __shared__ __align__(16) float sY[32][68];
    __shared__ __align__(16) float sW[32][68];
    const int lt = blockIdx.x*64, ct = blockIdx.y*64, b = blockIdx.z;
    const int tid = threadIdx.x;
    for (int i = tid; i < 32*16; i += 256) {
        int k = i>>4, j4 = (i&15)*4;
        float4 y0 = *(const float4*)&g_ym[((size_t)b*DM + k)*LL + lt + j4];
        float4 y1 = *(const float4*)&g_ym[((size_t)(NB+b)*DM + k)*LL + lt + j4];
        *(float4*)&sY[k][j4] = make_float4(y0.x+y1.x, y0.y+y1.y, y0.z+y1.z, y0.w+y1.w);
        *(float4*)&sW[k][j4] = *(const float4*)&W[k*128 + ct + j4];
    }
    __syncthreads();
    const int tl = (tid&15)*4, to = (tid>>4)*4;
    float acc[4][4] = {};
    #pragma unroll
    for (int k = 0; k < 32; k++) {
        float4 a = *(const float4*)&sW[k][to];
        float4 x = *(const float4*)&sY[k][tl];
        acc[0][0]+=a.x*x.x; acc[0][1]+=a.x*x.y; acc[0][2]+=a.x*x.z; acc[0][3]+=a.x*x.w;
        acc[1][0]+=a.y*x.x; acc[1][1]+=a.y*x.y; acc[1][2]+=a.y*x.z; acc[1][3]+=a.y*x.w;
        acc[2][0]+=a.z*x.x; acc[2][1]+=a.z*x.y; acc[2][2]+=a.z*x.z; acc[2][3]+=a.z*x.w;
        acc[3][0]+=a.w*x.x; acc[3][1]+=a.w*x.y; acc[3][2]+=a.w*x.z; acc[3][3]+=a.w*x.w;
    }
    #pragma unroll
    for (int i = 0; i < 4; i++)
        *(float4*)&g_o2[((size_t)b*NC + ct+to+i)*LL + lt+tl] =
            make_float4(acc[i][0],acc[i][1],acc[i][2],acc[i][3]);
}

__global__ void __launch_bounds__(128) bnstats1_kernel()
{
    const int c = blockIdx.x, b = blockIdx.y, tid = threadIdx.x;
    __shared__ float s1[128], s2[128];
    const float* pp = g_o2 + ((size_t)b*NC + c)*LL;
    float sum = 0.f, sq = 0.f;
    for (int i = tid*4; i < LL; i += 128*4) {
        float4 v = *(const float4*)&pp[i];
        sum += v.x+v.y+v.z+v.w;
        sq  += v.x*v.x+v.y*v.y+v.z*v.z+v.w*v.w;
    }
    s1[tid] = sum; s2[tid] = sq;
    __syncthreads();
    for (int st = 64; st > 0; st >>= 1) {
        if (tid < st) { s1[tid] += s1[tid+st]; s2[tid] += s2[tid+st]; }
        __syncthreads();
    }
    if (tid == 0) { g_red[(c*NB+b)*2] = s1[0]; g_red[(c*NB+b)*2+1] = s2[0]; }
}

__global__ void __launch_bounds__(128) bnstats2_kernel(
    const float* __restrict__ bng, const float* __restrict__ bnb)
{
    int c = threadIdx.x;
    float sum = 0.f, sq = 0.f;
    #pragma unroll
    for (int b = 0; b < NB; b++) { sum += g_red[(c*NB+b)*2]; sq += g_red[(c*NB+b)*2+1]; }
    float inv = 1.f/(float)(NB*LL);
    float mu  = sum*inv;
    float var = sq*inv - mu*mu;
    float ns  = bng[c]*rsqrtf(var + 1e-5f);
    g_ns[c] = ns;
    g_nb[c] = bnb[c] - mu*ns;
}

__global__ void foldA_kernel(const float* __restrict__ w)
{
    int i = blockIdx.x, o = threadIdx.x;
    g_Ap[i*128+o] = g_ns[i]*w[i*128+o];
}
__global__ void foldB_kernel(const float* __restrict__ w, const float* __restrict__ b4)
{
    int o = threadIdx.x;
    float s = b4[o];
    for (int i = 0; i < 128; i++) s += g_nb[i]*w[i*128+o];
    g_bp[o] = s;
}

extern "C" void kernel_launch(void* const* d_in, const int* in_sizes, int n_in,
                              void* d_out, int out_size)
{
    const float* x      = (const float*)d_in[0];
    const float* lin1_w = (const float*)d_in[1];
    const float* lin1_b = (const float*)d_in[2];
    const float* dw_w   = (const float*)d_in[3];
    const float* dw_b   = (const float*)d_in[4];
    const float* fcin_w = (const float*)d_in[5];
    const float* W_in   = (const float*)d_in[6];
    const float* convw  = (const float*)d_in[7];
    const float* convb  = (const float*)d_in[8];
    const float* dtb    = (const float*)d_in[9];
    const float* Alog   = (const float*)d_in[10];
    const float* Dp     = (const float*)d_in[11];
    const float* normw  = (const float*)d_in[12];
    const float* Wout   = (const float*)d_in[13];
    const float* fcow   = (const float*)d_in[14];
    const float* bng    = (const float*)d_in[15];
    const float* bnb    = (const float*)d_in[16];
    const float* c4w    = (const float*)d_in[17];
    const float* c4b    = (const float*)d_in[18];
    float* out = (float*)d_out;

    const int CP_SMEM = (67*SSS + 32*68 + 67*68 + 2*64*68 + 3*64)*4;
    const int CA_SMEM = (4*64*ST + 64*36 + 5*64)*4;
    cudaFuncSetAttribute(chunkprep_kernel, cudaFuncAttributeMaxDynamicSharedMemorySize, CP_SMEM);
    cudaFuncSetAttribute(chunkattn_kernel, cudaFuncAttributeMaxDynamicSharedMemorySize, CA_SMEM);

    gemm_cn_kernel<0><<<dim3(64,2,NB), 256>>>(lin1_w, x, lin1_b, nullptr, nullptr);
    dwconv_kernel<<<dim3(4,NC,NB), 256>>>(dw_w, dw_b);
    fcin_kernel<<<NB*32, 128>>>(fcin_w);
    chunkprep_kernel<<<dim3(NCHK,NB,2), 256, CP_SMEM>>>(W_in, convw, convb, dtb, Alog);
    hscan_kernel<<<dim3(4,16), 256>>>();
    chunkattn_kernel<<<dim3(NCHK,NB,2), 256, CA_SMEM>>>(Wout, normw, Dp);
    fcout_kernel<<<dim3(64,2,NB), 256>>>(fcow);
    bnstats1_kernel<<<dim3(NC,NB), 128>>>();
    bnstats2_kernel<<<1, NC>>>(bng, bnb);
    foldA_kernel<<<NC, NC>>>(c4w);
    foldB_kernel<<<1, NC>>>(c4w, c4b);
    gemm_cn_kernel<1><<<dim3(64,2,NB), 256>>>(nullptr, nullptr, nullptr, x, out);
}

// round 14
// speedup vs baseline: 1.5573x; 1.0860x over previous
#include <cuda_runtime.h>
#include <cuda_bf16.h>
#include <math.h>

#define NB   8
#define NC   128
#define LL   4096
#define DM   32
#define DI   64
#define DS   64
#define CHK  64
#define NCHK 64

__device__ float g_out1[NB*NC*LL];
__device__ float g_act [NB*NC*LL];
__device__ float g_s   [NB*LL*DM];
__device__ float g_z   [2*NB*LL*DI];
__device__ float g_X   [2*NB*LL*DI];
__device__ float g_Bm  [2*NB*LL*DS];
__device__ float g_Cm  [2*NB*LL*DS];
__device__ float g_dt  [2*NB*LL];
__device__ float g_la  [2*NB*LL];
__device__ float g_alpha[2*NB*NCHK];
__device__ float g_S   [2*NB*NCHK*DI*DS];
__device__ float g_Hp  [2*NB*NCHK*DI*DS];
__device__ float g_ym  [2*NB*DM*LL];      // [bd][dm][l]
__device__ float g_o2  [NB*NC*LL];
__device__ float g_red [NC*NB*2];
__device__ float g_ns[NC], g_nb[NC];
__device__ float g_Ap[NC*NC];
__device__ float g_bp[NC];

__device__ __forceinline__ float siluf(float v){ return v / (1.f + __expf(-v)); }

__device__ __forceinline__ unsigned tf32cvt(float f){
    unsigned r; asm("cvt.rna.tf32.f32 %0, %1;" : "=r"(r) : "f"(f)); return r;
}
__device__ __forceinline__ void mma8(float* c, unsigned a0, unsigned a1, unsigned a2, unsigned a3,
                                     unsigned b0, unsigned b1){
    asm("mma.sync.aligned.m16n8k8.row.col.f32.tf32.tf32.f32 "
        "{%0,%1,%2,%3},{%4,%5,%6,%7},{%8,%9},{%0,%1,%2,%3};"
        : "+f"(c[0]),"+f"(c[1]),"+f"(c[2]),"+f"(c[3])
        : "r"(a0),"r"(a1),"r"(a2),"r"(a3),"r"(b0),"r"(b1));
}

// out[bb,o,l] = f( sum_i A[i,o]*Xin[bb,i,l] + bias[o] )  -- tf32 tensor core
template<int MODE>
__global__ void __launch_bounds__(256) gemm_cn_kernel(
    const float* __restrict__ Aext, const float* __restrict__ Xext,
    const float* __restrict__ bext, const float* __restrict__ resx,
    float* __restrict__ outext)
{
    const float* A    = (MODE==0) ? Aext : g_Ap;
    const float* Xin  = (MODE==0) ? Xext : g_o2;
    const float* bias = (MODE==0) ? bext : g_bp;
    float*       out  = (MODE==0) ? g_out1 : outext;

    const int lt = blockIdx.x*64, ot = blockIdx.y*64, bb = blockIdx.z;
    __shared__ __align__(16) unsigned sA[32*72];
    __shared__ __align__(16) unsigned sX[32*72];
    const int tid = threadIdx.x;
    const int w = tid>>5, lane = tid&31, g = lane>>2, tg = lane&3;
    const int wo = (w&1)*32, wl = (w>>1)*16;
    float c[2][2][4] = {};
    const float* Xb = Xin + (size_t)bb*NC*LL;

    for (int k0 = 0; k0 < 128; k0 += 32) {
        for (int i = tid; i < 32*16; i += 256) {
            int kk = i>>4, j4 = (i&15)*4;
            float4 av = *(const float4*)&A[(k0+kk)*128 + ot + j4];
            float4 xv = *(const float4*)&Xb[(size_t)(k0+kk)*LL + lt + j4];
            sA[kk*72+j4+0]=tf32cvt(av.x); sA[kk*72+j4+1]=tf32cvt(av.y);
            sA[kk*72+j4+2]=tf32cvt(av.z); sA[kk*72+j4+3]=tf32cvt(av.w);
            sX[kk*72+j4+0]=tf32cvt(xv.x); sX[kk*72+j4+1]=tf32cvt(xv.y);
            sX[kk*72+j4+2]=tf32cvt(xv.z); sX[kk*72+j4+3]=tf32cvt(xv.w);
        }
        __syncthreads();
        #pragma unroll
        for (int kk = 0; kk < 32; kk += 8) {
            unsigned a[2][4], bfr[2][2];
            #pragma unroll
            for (int os = 0; os < 2; os++) {
                int ob = wo + os*16 + g;
                a[os][0] = sA[(kk+tg)*72 + ob];
                a[os][1] = sA[(kk+tg)*72 + ob+8];
                a[os][2] = sA[(kk+tg+4)*72 + ob];
                a[os][3] = sA[(kk+tg+4)*72 + ob+8];
            }
            #pragma unroll
            for (int ls = 0; ls < 2; ls++) {
                int lb = wl + ls*8 + g;
                bfr[ls][0] = sX[(kk+tg)*72 + lb];
                bfr[ls][1] = sX[(kk+tg+4)*72 + lb];
            }
            #pragma unroll
            for (int os = 0; os < 2; os++)
                #pragma unroll
                for (int ls = 0; ls < 2; ls++)
                    mma8(c[os][ls], a[os][0],a[os][1],a[os][2],a[os][3],
                         bfr[ls][0], bfr[ls][1]);
        }
        __syncthreads();
    }
    #pragma unroll
    for (int os = 0; os < 2; os++)
        #pragma unroll
        for (int half = 0; half < 2; half++) {
            int o = ot + wo + os*16 + g + half*8;
            float bv = bias[o];
            #pragma unroll
            for (int ls = 0; ls < 2; ls++) {
                int l = lt + wl + ls*8 + 2*tg;
                size_t idx = ((size_t)bb*NC + o)*LL + l;
                float v0 = c[os][ls][half*2+0] + bv;
                float v1 = c[os][ls][half*2+1] + bv;
                if (MODE == 1) {
                    float2 xv = *(const float2*)&resx[idx];
                    v0 = xv.x/(1.f+__expf(-v0)) + xv.x;
                    v1 = xv.y/(1.f+__expf(-v1)) + xv.y;
                }
                *(float2*)&out[idx] = make_float2(v0, v1);
            }
        }
}

__global__ void __launch_bounds__(256) dwconv_kernel(
    const float* __restrict__ w, const float* __restrict__ bias)
{
    const int b = blockIdx.z, c = blockIdx.y, st = blockIdx.x;
    __shared__ float tile[18][66];
    const float* inp = g_out1 + ((size_t)b*NC + c)*LL;
    const int h0 = st*16;
    for (int i = threadIdx.x; i < 18*66; i += 256) {
        int r = i/66, q = i%66;
        int h = h0 + r - 1, wq = q - 1;
        tile[r][q] = (h>=0 && h<64 && wq>=0 && wq<64) ? inp[h*64+wq] : 0.f;
    }
    __syncthreads();
    const float* wc = w + c*9;
    const float bb = bias[c];
    for (int i = threadIdx.x; i < 16*64; i += 256) {
        int r = i>>6, q = i&63;
        float v = wc[0]*tile[r][q]   + wc[1]*tile[r][q+1]   + wc[2]*tile[r][q+2]
                + wc[3]*tile[r+1][q] + wc[4]*tile[r+1][q+1] + wc[5]*tile[r+1][q+2]
                + wc[6]*tile[r+2][q] + wc[7]*tile[r+2][q+1] + wc[8]*tile[r+2][q+2] + bb;
        g_act[((size_t)b*NC + c)*LL + (h0+r)*64 + q] = siluf(v);
    }
}

__global__ void __launch_bounds__(128) fcin_kernel(const float* __restrict__ w)
{
    __shared__ float sw[NC*DM];
    for (int i = threadIdx.x; i < NC*DM; i += 128) sw[i] = w[i];
    __syncthreads();
    const int b = blockIdx.x / 32;
    const int l = (blockIdx.x % 32)*128 + threadIdx.x;
    const float* ap = g_act + (size_t)b*NC*LL + l;
    float acc[DM] = {};
    for (int c = 0; c < NC; c++) {
        float v = ap[(size_t)c*LL];
        #pragma unroll
        for (int d = 0; d < DM; d++) acc[d] += v*sw[c*DM+d];
    }
    float* sp = g_s + ((size_t)b*LL + l)*DM;
    #pragma unroll
    for (int d = 0; d < DM; d++) sp[d] = acc[d];
}

#define SSS 36
__global__ void __launch_bounds__(256) chunkprep_kernel(
    const float* __restrict__ W_in, const float* __restrict__ convw,
    const float* __restrict__ convb, const float* __restrict__ dtb,
    const float* __restrict__ Alog)
{
    extern __shared__ float sm[];
    float* sS  = sm;                 // 67*36
    float* sW  = sS + 67*SSS;        // 32*68
    float* sT  = sW + 32*68;         // 67*68
    float* sX  = sT + 67*68;         // 64*68
    float* sB  = sX + 64*68;         // 64*68
    float* sdt = sB + 64*68;         // 64
    float* sla = sdt + 64;           // 64
    float* swt = sla + 64;           // 64

    const int c = blockIdx.x, b = blockIdx.y, d = blockIdx.z;
    const int tid = threadIdx.x;
    const int t0 = c*CHK;
    const int bd = d*NB + b;
    const int ti = (tid>>4)*4, sj = (tid&15)*4;

    for (int i = tid; i < 67*32; i += 256) {
        int u = i>>5, k = i&31;
        int t = t0 + u - 3;
        float v = 0.f;
        if (t >= 0) {
            int l = d ? (LL-1-t) : t;
            v = g_s[((size_t)b*LL + l)*DM + k];
        }
        sS[u*SSS+k] = v;
    }
    const float* Wd = W_in + d*32*257;

    for (int tile = 0; tile < 4; tile++) {
        __syncthreads();
        for (int i = tid; i < 32*64; i += 256) {
            int k = i>>6, j = i&63;
            sW[k*68+j] = Wd[k*257 + tile*64 + j];
        }
        __syncthreads();
        {
            float acc[4][4] = {};
            #pragma unroll
            for (int k0 = 0; k0 < 32; k0 += 4) {
                float a4[4][4];
                #pragma unroll
                for (int i = 0; i < 4; i++) {
                    float4 t4 = *(const float4*)&sS[(ti+i)*SSS+k0];
                    a4[i][0]=t4.x; a4[i][1]=t4.y; a4[i][2]=t4.z; a4[i][3]=t4.w;
                }
                #pragma unroll
                for (int kk = 0; kk < 4; kk++) {
                    float4 b4 = *(const float4*)&sW[(k0+kk)*68+sj];
                    #pragma unroll
                    for (int i = 0; i < 4; i++) {
                        acc[i][0] += a4[i][kk]*b4.x;
                        acc[i][1] += a4[i][kk]*b4.y;
                        acc[i][2] += a4[i][kk]*b4.z;
                        acc[i][3] += a4[i][kk]*b4.w;
                    }
                }
            }
            #pragma unroll
            for (int i = 0; i < 4; i++)
                *(float4*)&sT[(ti+i)*68+sj] = make_float4(acc[i][0],acc[i][1],acc[i][2],acc[i][3]);
            if (tid < 192) {
                int u = 64 + (tid>>6), j = tid&63;
                float a = 0.f;
                #pragma unroll
                for (int k = 0; k < 32; k++) a += sS[u*SSS+k]*sW[k*68+j];
                sT[u*68+j] = a;
            }
        }
        __syncthreads();
        if (tile == 0) {
            for (int i = tid; i < 64*64; i += 256) {
                int t = i>>6, j = i&63;
                g_z[((size_t)bd*LL + t0 + t)*DI + j] = sT[(t+3)*68+j];
            }
        } else {
            for (int i = tid; i < 64*64; i += 256) {
                int t = i>>6, j = i&63;
                int ch = (tile-1)*64 + j;
                const float* cw = convw + (d*192 + ch)*4;
                float v = cw[0]*sT[t*68+j] + cw[1]*sT[(t+1)*68+j]
                        + cw[2]*sT[(t+2)*68+j] + cw[3]*sT[(t+3)*68+j]
                        + convb[d*192 + ch];
                v = siluf(v);
                size_t gi = ((size_t)bd*LL + t0 + t)*DI + j;
                if      (tile == 1) { sX[t*68+j] = v; g_X[gi]  = v; }
                else if (tile == 2) { sB[t*68+j] = v; g_Bm[gi] = v; }
                else                {                 g_Cm[gi] = v; }
            }
        }
    }
    __syncthreads();

    if (tid < 64) {
        float a = 0.f;
        #pragma unroll
        for (int k = 0; k < 32; k++) a += sS[(tid+3)*SSS+k]*Wd[k*257+256];
        a += dtb[d];
        float dt = (a > 20.f) ? a : log1pf(__expf(a));
        sdt[tid] = dt;
        g_dt[(size_t)bd*LL + t0 + tid] = dt;
    }
    __syncthreads();
    if (tid == 0) {
        float eA = __expf(Alog[d]);
        float run = 0.f;
        for (int t = 0; t < 64; t++) { run -= sdt[t]*eA; sla[t] = run; }
        g_alpha[bd*NCHK + c] = __expf(run);
    }
    __syncthreads();
    if (tid < 64) {
        swt[tid] = __expf(sla[63] - sla[tid])*sdt[tid];
        g_la[(size_t)bd*LL + t0 + tid] = sla[tid];
    }
    __syncthreads();
    for (int i = tid; i < 64*64; i += 256) {
        int s_ = i>>6;
        sX[s_*68 + (i&63)] *= swt[s_];
    }
    __syncthreads();
    {
        float acc[4][4] = {};
        #pragma unroll 8
        for (int s_ = 0; s_ < 64; s_++) {
            float4 xa = *(const float4*)&sX[s_*68+ti];
            float4 bv = *(const float4*)&sB[s_*68+sj];
            acc[0][0]+=xa.x*bv.x; acc[0][1]+=xa.x*bv.y; acc[0][2]+=xa.x*bv.z; acc[0][3]+=xa.x*bv.w;
            acc[1][0]+=xa.y*bv.x; acc[1][1]+=xa.y*bv.y; acc[1][2]+=xa.y*bv.z; acc[1][3]+=xa.y*bv.w;
            acc[2][0]+=xa.z*bv.x; acc[2][1]+=xa.z*bv.y; acc[2][2]+=xa.z*bv.z; acc[2][3]+=xa.z*bv.w;
            acc[3][0]+=xa.w*bv.x; acc[3][1]+=xa.w*bv.y; acc[3][2]+=xa.w*bv.z; acc[3][3]+=xa.w*bv.w;
        }
        float* Sp = g_S + ((size_t)bd*NCHK + c)*4096;
        #pragma unroll
        for (int i = 0; i < 4; i++)
            *(float4*)&Sp[(ti+i)*64+sj] = make_float4(acc[i][0],acc[i][1],acc[i][2],acc[i][3]);
    }
}

__global__ void __launch_bounds__(256) hscan_kernel()
{
    const int bd = blockIdx.y;
    const int cell = (blockIdx.x*256 + threadIdx.x)*4;
    const float* Sp = g_S  + (size_t)bd*NCHK*4096 + cell;
    float*       Hp = g_Hp + (size_t)bd*NCHK*4096 + cell;
    const float* al = g_alpha + bd*NCHK;
    float4 h = make_float4(0.f,0.f,0.f,0.f);
    #pragma unroll 8
    for (int c = 0; c < NCHK; c++) {
        *(float4*)&Hp[(size_t)c*4096] = h;
        float a = al[c];
        float4 s = *(const float4*)&Sp[(size_t)c*4096];
        h.x = a*h.x + s.x; h.y = a*h.y + s.y; h.z = a*h.z + s.z; h.w = a*h.w + s.w;
    }
}

#define ST 68
__global__ void __launch_bounds__(256) chunkattn_kernel(
    const float* __restrict__ Wout, const float* __restrict__ normw,
    const float* __restrict__ Dp)
{
    extern __shared__ float sm2[];
    float* sC   = sm2;            // 64*ST
    float* sBT  = sC + 64*ST;     // 64*ST : B^T [n][t], then Hprev^T [n][p]
    float* sG   = sBT + 64*ST;    // 64*ST : G, then silu(z)
    float* sX   = sG + 64*ST;     // 64*ST : X, then gated Y
    float* sWo  = sX + 64*ST;     // 64*36
    float* snw  = sWo + 64*36;
    float* srms = snw + 64;
    float* slaL = srms + 64;
    float* sdtL = slaL + 64;
    float* sef  = sdtL + 64;

    const int c = blockIdx.x, b = blockIdx.y, d = blockIdx.z;
    const int tid = threadIdx.x;
    const int bd = d*NB + b;
    const int t0 = c*CHK;
    const size_t base = ((size_t)bd*LL + t0)*DI;

    const int w = tid>>5, lane = tid&31, g = lane>>2, tg = lane&3;
    const int tt = (w&3)*16, cc = (w>>2)*32;

    for (int i = tid; i < 64*64; i += 256) {
        int t = i>>6, n = i&63;
        sC[t*ST+n]  = g_Cm[base+i];
        sBT[n*ST+t] = g_Bm[base+i];
        sX[t*ST+n]  = g_X [base+i];
    }
    for (int i = tid; i < 64*32; i += 256)
        sWo[(i>>5)*36 + (i&31)] = Wout[d*2048 + i];
    if (tid < 64) {
        snw[tid]  = normw[d*64 + tid];
        slaL[tid] = g_la[(size_t)bd*LL + t0 + tid];
        sdtL[tid] = g_dt[(size_t)bd*LL + t0 + tid];
        sef[tid]  = __expf(slaL[tid]);
    }
    __syncthreads();

    // pass1: M[t][s] = C_t . B_s  (tf32 mma)
    {
        float m[4][4] = {};
        #pragma unroll
        for (int kk = 0; kk < 64; kk += 8) {
            unsigned a0 = tf32cvt(sC[(tt+g)*ST + kk+tg]);
            unsigned a1 = tf32cvt(sC[(tt+g+8)*ST + kk+tg]);
            unsigned a2 = tf32cvt(sC[(tt+g)*ST + kk+tg+4]);
            unsigned a3 = tf32cvt(sC[(tt+g+8)*ST + kk+tg+4]);
            #pragma unroll
            for (int ns = 0; ns < 4; ns++) {
                unsigned b0 = tf32cvt(sBT[(kk+tg)*ST + cc+ns*8+g]);
                unsigned b1 = tf32cvt(sBT[(kk+tg+4)*ST + cc+ns*8+g]);
                mma8(m[ns], a0,a1,a2,a3, b0,b1);
            }
        }
        #pragma unroll
        for (int ns = 0; ns < 4; ns++)
            #pragma unroll
            for (int cr = 0; cr < 4; cr++) {
                int t = tt + g + ((cr>=2)?8:0);
                int s = cc + ns*8 + 2*tg + (cr&1);
                sG[t*ST+s] = (t >= s) ? m[ns][cr]*sdtL[s]*__expf(slaL[t]-slaL[s]) : 0.f;
            }
    }
    __syncthreads();

    for (int i = tid; i < 64*64; i += 256) {
        int t = i>>6;
        sC[t*ST + (i&63)] *= sef[t];
    }
    {
        const float* Hp = g_Hp + ((size_t)bd*NCHK + c)*4096;
        for (int i = tid; i < 64*64; i += 256)
            sBT[(i&63)*ST + (i>>6)] = Hp[i];   // HpT[n][p]
    }
    __syncthreads();

    float y[4][4];
    const float Dv = Dp[d];
    #pragma unroll
    for (int ns = 0; ns < 4; ns++)
        #pragma unroll
        for (int cr = 0; cr < 4; cr++) {
            int t = tt + g + ((cr>=2)?8:0);
            int p = cc + ns*8 + 2*tg + (cr&1);
            y[ns][cr] = Dv * sX[t*ST+p];
        }
    // pass2: Y += G @ X
    #pragma unroll
    for (int kk = 0; kk < 64; kk += 8) {
        unsigned a0 = tf32cvt(sG[(tt+g)*ST + kk+tg]);
        unsigned a1 = tf32cvt(sG[(tt+g+8)*ST + kk+tg]);
        unsigned a2 = tf32cvt(sG[(tt+g)*ST + kk+tg+4]);
        unsigned a3 = tf32cvt(sG[(tt+g+8)*ST + kk+tg+4]);
        #pragma unroll
        for (int ns = 0; ns < 4; ns++) {
            unsigned b0 = tf32cvt(sX[(kk+tg)*ST + cc+ns*8+g]);
            unsigned b1 = tf32cvt(sX[(kk+tg+4)*ST + cc+ns*8+g]);
            mma8(y[ns], a0,a1,a2,a3, b0,b1);
        }
    }
    // pass3: Y += (exp(la)*C) @ Hprev^T
    #pragma unroll
    for (int kk = 0; kk < 64; kk += 8) {
        unsigned a0 = tf32cvt(sC[(tt+g)*ST + kk+tg]);
        unsigned a1 = tf32cvt(sC[(tt+g+8)*ST + kk+tg]);
        unsigned a2 = tf32cvt(sC[(tt+g)*ST + kk+tg+4]);
        unsigned a3 = tf32cvt(sC[(tt+g+8)*ST + kk+tg+4]);
        #pragma unroll
        for (int ns = 0; ns < 4; ns++) {
            unsigned b0 = tf32cvt(sBT[(kk+tg)*ST + cc+ns*8+g]);
            unsigned b1 = tf32cvt(sBT[(kk+tg+4)*ST + cc+ns*8+g]);
            mma8(y[ns], a0,a1,a2,a3, b0,b1);
        }
    }
    __syncthreads();
    for (int i = tid; i < 64*64; i += 256)
        sG[(i>>6)*ST + (i&63)] = siluf(g_z[base+i]);
    __syncthreads();
    #pragma unroll
    for (int ns = 0; ns < 4; ns++)
        #pragma unroll
        for (int cr = 0; cr < 4; cr++) {
            int t = tt + g + ((cr>=2)?8:0);
            int p = cc + ns*8 + 2*tg + (cr&1);
            float v = y[ns][cr] * sG[t*ST+p];
            sX[t*ST+p] = v;
        }
    __syncthreads();
    if (tid < 64) {
        float ss = 0.f;
        #pragma unroll
        for (int p = 0; p < 64; p++){ float v = sX[tid*ST+p]; ss += v*v; }
        srms[tid] = rsqrtf(ss*(1.f/64.f) + 1e-5f);
    }
    __syncthreads();
    for (int i = tid; i < 64*64; i += 256) {
        int t = i>>6, p = i&63;
        sX[t*ST+p] *= srms[t]*snw[p];
    }
    __syncthreads();
    {
        int t = tid>>2, q = (tid&3)*8;
        float acc[8] = {};
        #pragma unroll 8
        for (int p = 0; p < 64; p++) {
            float v = sX[t*ST+p];
            float4 w0 = *(const float4*)&sWo[p*36+q];
            float4 w1 = *(const float4*)&sWo[p*36+q+4];
            acc[0]+=v*w0.x; acc[1]+=v*w0.y; acc[2]+=v*w0.z; acc[3]+=v*w0.w;
            acc[4]+=v*w1.x; acc[5]+=v*w1.y; acc[6]+=v*w1.z; acc[7]+=v*w1.w;
        }
        int l = d ? (LL-1-(t0+t)) : (t0+t);
        #pragma unroll
        for (int j = 0; j < 8; j++)
            g_ym[((size_t)bd*DM + q + j)*LL + l] = acc[j];
    }
}

__global__ void __launch_bounds__(256) fcout_kernel(const float* __restrict__ W)
{
    __shared__ __align__(16) float sY[32][68];
    __shared__ __align__(16) float sW[32][68];
    const int lt = blockIdx.x*64, ct = blockIdx.y*64, b = blockIdx.z;
    const int tid = threadIdx.x;
    for (int i = tid; i < 32*16; i += 256) {
        int k = i>>4, j4 = (i&15)*4;
        float4 y0 = *(const float4*)&g_ym[((size_t)b*DM + k)*LL + lt + j4];
        float4 y1 = *(const float4*)&g_ym[((size_t)(NB+b)*DM + k)*LL + lt + j4];
        *(float4*)&sY[k][j4] = make_float4(y0.x+y1.x, y0.y+y1.y, y0.z+y1.z, y0.w+y1.w);
        *(float4*)&sW[k][j4] = *(const float4*)&W[k*128 + ct + j4];
    }
    __syncthreads();
    const int tl = (tid&15)*4, to = (tid>>4)*4;
    float acc[4][4] = {};
    #pragma unroll
    for (int k = 0; k < 32; k++) {
        float4 a = *(const float4*)&sW[k][to];
        float4 x = *(const float4*)&sY[k][tl];
        acc[0][0]+=a.x*x.x; acc[0][1]+=a.x*x.y; acc[0][2]+=a.x*x.z; acc[0][3]+=a.x*x.w;
        acc[1][0]+=a.y*x.x; acc[1][1]+=a.y*x.y; acc[1][2]+=a.y*x.z; acc[1][3]+=a.y*x.w;
        acc[2][0]+=a.z*x.x; acc[2][1]+=a.z*x.y; acc[2][2]+=a.z*x.z; acc[2][3]+=a.z*x.w;
        acc[3][0]+=a.w*x.x; acc[3][1]+=a.w*x.y; acc[3][2]+=a.w*x.z; acc[3][3]+=a.w*x.w;
    }
    #pragma unroll
    for (int i = 0; i < 4; i++)
        *(float4*)&g_o2[((size_t)b*NC + ct+to+i)*LL + lt+tl] =
            make_float4(acc[i][0],acc[i][1],acc[i][2],acc[i][3]);
}

__global__ void __launch_bounds__(128) bnstats1_kernel()
{
    const int c = blockIdx.x, b = blockIdx.y, tid = threadIdx.x;
    __shared__ float s1[128], s2[128];
    const float* pp = g_o2 + ((size_t)b*NC + c)*LL;
    float sum = 0.f, sq = 0.f;
    for (int i = tid*4; i < LL; i += 128*4) {
        float4 v = *(const float4*)&pp[i];
        sum += v.x+v.y+v.z+v.w;
        sq  += v.x*v.x+v.y*v.y+v.z*v.z+v.w*v.w;
    }
    s1[tid] = sum; s2[tid] = sq;
    __syncthreads();
    for (int st = 64; st > 0; st >>= 1) {
        if (tid < st) { s1[tid] += s1[tid+st]; s2[tid] += s2[tid+st]; }
        __syncthreads();
    }
    if (tid == 0) { g_red[(c*NB+b)*2] = s1[0]; g_red[(c*NB+b)*2+1] = s2[0]; }
}

__global__ void __launch_bounds__(128) bnstats2_kernel(
    const float* __restrict__ bng, const float* __restrict__ bnb)
{
    int c = threadIdx.x;
    float sum = 0.f, sq = 0.f;
    #pragma unroll
    for (int b = 0; b < NB; b++) { sum += g_red[(c*NB+b)*2]; sq += g_red[(c*NB+b)*2+1]; }
    float inv = 1.f/(float)(NB*LL);
    float mu  = sum*inv;
    float var = sq*inv - mu*mu;
    float ns  = bng[c]*rsqrtf(var + 1e-5f);
    g_ns[c] = ns;
    g_nb[c] = bnb[c] - mu*ns;
}

__global__ void foldA_kernel(const float* __restrict__ w)
{
    int i = blockIdx.x, o = threadIdx.x;
    g_Ap[i*128+o] = g_ns[i]*w[i*128+o];
}
__global__ void foldB_kernel(const float* __restrict__ w, const float* __restrict__ b4)
{
    int o = threadIdx.x;
    float s = b4[o];
    for (int i = 0; i < 128; i++) s += g_nb[i]*w[i*128+o];
    g_bp[o] = s;
}

extern "C" void kernel_launch(void* const* d_in, const int* in_sizes, int n_in,
                              void* d_out, int out_size)
{
    const float* x      = (const float*)d_in[0];
    const float* lin1_w = (const float*)d_in[1];
    const float* lin1_b = (const float*)d_in[2];
    const float* dw_w   = (const float*)d_in[3];
    const float* dw_b   = (const float*)d_in[4];
    const float* fcin_w = (const float*)d_in[5];
    const float* W_in   = (const float*)d_in[6];
    const float* convw  = (const float*)d_in[7];
    const float* convb  = (const float*)d_in[8];
    const float* dtb    = (const float*)d_in[9];
    const float* Alog   = (const float*)d_in[10];
    const float* Dp     = (const float*)d_in[11];
    const float* normw  = (const float*)d_in[12];
    const float* Wout   = (const float*)d_in[13];
    const float* fcow   = (const float*)d_in[14];
    const float* bng    = (const float*)d_in[15];
    const float* bnb    = (const float*)d_in[16];
    const float* c4w    = (const float*)d_in[17];
    const float* c4b    = (const float*)d_in[18];
    float* out = (float*)d_out;

    const int CP_SMEM = (67*SSS + 32*68 + 67*68 + 2*64*68 + 3*64)*4;
    const int CA_SMEM = (4*64*ST + 64*36 + 5*64)*4;
    cudaFuncSetAttribute(chunkprep_kernel, cudaFuncAttributeMaxDynamicSharedMemorySize, CP_SMEM);
    cudaFuncSetAttribute(chunkattn_kernel, cudaFuncAttributeMaxDynamicSharedMemorySize, CA_SMEM);

    gemm_cn_kernel<0><<<dim3(64,2,NB), 256>>>(lin1_w, x, lin1_b, nullptr, nullptr);
    dwconv_kernel<<<dim3(4,NC,NB), 256>>>(dw_w, dw_b);
    fcin_kernel<<<NB*32, 128>>>(fcin_w);
    chunkprep_kernel<<<dim3(NCHK,NB,2), 256, CP_SMEM>>>(W_in, convw, convb, dtb, Alog);
    hscan_kernel<<<dim3(4,16), 256>>>();
    chunkattn_kernel<<<dim3(NCHK,NB,2), 256, CA_SMEM>>>(Wout, normw, Dp);
    fcout_kernel<<<dim3(64,2,NB), 256>>>(fcow);
    bnstats1_kernel<<<dim3(NC,NB), 128>>>();
    bnstats2_kernel<<<1, NC>>>(bng, bnb);
    foldA_kernel<<<NC, NC>>>(c4w);
    foldB_kernel<<<1, NC>>>(c4w, c4b);
    gemm_cn_kernel<1><<<dim3(64,2,NB), 256>>>(nullptr, nullptr, nullptr, x, out);
}